// round 7
// baseline (speedup 1.0000x reference)
#include <cuda_runtime.h>
#include <math.h>

#define BATCH   2
#define LSEQ    2048
#define MTOK    (BATCH*LSEQ)          // 4096
#define DMODEL  2048
#define DINNER  2048
#define NH      32
#define DSTATE  64
#define HD      64
#define CHUNK   128
#define NCHUNK  (LSEQ/CHUNK)          // 16
#define DFF     8192
#define CONVD   (DINNER + 2*NH*DSTATE)          // 6144
#define DINPROJ (2*DINNER + 2*NH*DSTATE + NH)   // 8224
#define DTOFF   (DINNER + CONVD)                // 8192

// ------------------------- scratch (device globals, no allocs) -------------
__device__ float g_h1  [(size_t)MTOK*DMODEL];
__device__ float g_zx  [(size_t)MTOK*DINPROJ];
__device__ float g_xBC [(size_t)MTOK*CONVD];
__device__ float g_y   [(size_t)MTOK*DINNER];
__device__ float g_S   [(size_t)BATCH*NCHUNK*NH*DSTATE*HD];
__device__ float g_Ac  [(size_t)BATCH*NCHUNK*NH];
__device__ float g_cum [(size_t)BATCH*NCHUNK*NH*CHUNK];
__device__ float g_Hp  [(size_t)BATCH*NCHUNK*NH*DSTATE*HD];
__device__ float g_h2  [(size_t)MTOK*DMODEL];
__device__ float g_h3  [(size_t)MTOK*DMODEL];
__device__ float g_gate[(size_t)MTOK*DFF];
__device__ float g_up  [(size_t)MTOK*DFF];

// ------------------------------ rmsnorm ------------------------------------
__global__ void rmsnorm_kernel(const float* __restrict__ x, const float* __restrict__ w,
                               float* __restrict__ y) {
    int row = blockIdx.x;
    const float* xr = x + (size_t)row * DMODEL;
    float ss = 0.f;
    for (int c = threadIdx.x; c < DMODEL; c += 256) { float v = xr[c]; ss += v * v; }
    #pragma unroll
    for (int off = 16; off; off >>= 1) ss += __shfl_xor_sync(0xffffffffu, ss, off);
    __shared__ float red[8];
    if ((threadIdx.x & 31) == 0) red[threadIdx.x >> 5] = ss;
    __syncthreads();
    if (threadIdx.x < 8) {
        float v = red[threadIdx.x];
        #pragma unroll
        for (int off = 4; off; off >>= 1) v += __shfl_xor_sync(0xffu, v, off);
        if (threadIdx.x == 0) red[0] = v;
    }
    __syncthreads();
    float inv = rsqrtf(red[0] / (float)DMODEL + 1e-5f);
    float* yr = y + (size_t)row * DMODEL;
    for (int c = threadIdx.x; c < DMODEL; c += 256) yr[c] = w[c] * xr[c] * inv;
}

// ------------------------------ SGEMM (C = A * W^T [+ res]) ----------------
// A: [M,K] row-major, W: [N,K] row-major, C: [M,N]. 128x128 tile, BK=16,
// 256 threads, 8x8 per thread. M % 128 == 0, K % 16 == 0, N guarded.
__global__ void sgemm_nt_kernel(const float* __restrict__ A, const float* __restrict__ W,
                                const float* __restrict__ res, float* __restrict__ C,
                                int M, int N, int K) {
    __shared__ float As[16][129];
    __shared__ float Ws[16][129];
    int tid = threadIdx.x;
    int bm = blockIdx.y * 128, bn = blockIdx.x * 128;
    int ty = tid >> 4, tx = tid & 15;
    int lr = tid >> 2;            // 0..63
    int lc = (tid & 3) * 4;       // 0,4,8,12

    float acc[8][8];
    #pragma unroll
    for (int r = 0; r < 8; r++)
        #pragma unroll
        for (int s = 0; s < 8; s++) acc[r][s] = 0.f;

    for (int k0 = 0; k0 < K; k0 += 16) {
        #pragma unroll
        for (int pass = 0; pass < 2; pass++) {
            int r = lr + pass * 64;
            float4 av = *(const float4*)(A + (size_t)(bm + r) * K + k0 + lc);
            As[lc + 0][r] = av.x; As[lc + 1][r] = av.y;
            As[lc + 2][r] = av.z; As[lc + 3][r] = av.w;
            int n = bn + r;
            float4 wv = make_float4(0.f, 0.f, 0.f, 0.f);
            if (n < N) wv = *(const float4*)(W + (size_t)n * K + k0 + lc);
            Ws[lc + 0][r] = wv.x; Ws[lc + 1][r] = wv.y;
            Ws[lc + 2][r] = wv.z; Ws[lc + 3][r] = wv.w;
        }
        __syncthreads();
        #pragma unroll
        for (int kk = 0; kk < 16; kk++) {
            float af[8], bf[8];
            #pragma unroll
            for (int r = 0; r < 8; r++) af[r] = As[kk][ty * 8 + r];
            #pragma unroll
            for (int s = 0; s < 8; s++) bf[s] = Ws[kk][tx * 8 + s];
            #pragma unroll
            for (int r = 0; r < 8; r++)
                #pragma unroll
                for (int s = 0; s < 8; s++) acc[r][s] += af[r] * bf[s];
        }
        __syncthreads();
    }
    #pragma unroll
    for (int r = 0; r < 8; r++) {
        int m = bm + ty * 8 + r;
        #pragma unroll
        for (int s = 0; s < 8; s++) {
            int n = bn + tx * 8 + s;
            if (n < N) {
                float v = acc[r][s];
                if (res) v += res[(size_t)m * N + n];
                C[(size_t)m * N + n] = v;
            }
        }
    }
}

// ------------------------------ causal depthwise conv ----------------------
__global__ void conv1d_kernel(const float* __restrict__ zx, const float* __restrict__ cw,
                              const float* __restrict__ cb, float* __restrict__ xBC) {
    size_t idx = (size_t)blockIdx.x * blockDim.x + threadIdx.x;
    if (idx >= (size_t)MTOK * CONVD) return;
    int c = (int)(idx % CONVD);
    int m = (int)(idx / CONVD);
    int t = m & (LSEQ - 1);           // position within sequence
    float acc = cb[c];
    #pragma unroll
    for (int j = 0; j < 4; j++) {
        int tt = t - 3 + j;
        if (tt >= 0)
            acc += cw[c * 4 + j] * zx[(size_t)(m - 3 + j) * DINPROJ + DINNER + c];
    }
    xBC[idx] = acc;
}

// ------------------------------ SSD intra-chunk ----------------------------
// one block per (b, chunk, head). Computes y_intra, chunk state S, A_chunk, cum.
__global__ void ssd_intra_kernel(const float* __restrict__ zx, const float* __restrict__ xBC,
                                 float* __restrict__ y, float* __restrict__ Sg,
                                 float* __restrict__ Ag, float* __restrict__ cumg) {
    extern __shared__ float sm[];
    float* xs   = sm;                       // 128*65
    float* Bs   = xs + CHUNK * 65;          // 128*65
    float* Cs   = Bs + CHUNK * 65;          // 128*65
    float* sc   = Cs + CHUNK * 65;          // 128*129
    float* cum  = sc + CHUNK * 129;         // 128
    float* dend = cum + CHUNK;              // 128

    int h = blockIdx.x % NH;
    int c = (blockIdx.x / NH) % NCHUNK;
    int b = blockIdx.x / (NH * NCHUNK);
    int tid = threadIdx.x;
    int m0 = b * LSEQ + c * CHUNK;

    for (int idx = tid; idx < CHUNK * HD; idx += 256) {
        int i = idx >> 6, p = idx & 63;
        size_t rowb = (size_t)(m0 + i) * CONVD;
        xs[i * 65 + p] = xBC[rowb + h * HD + p];
        Bs[i * 65 + p] = xBC[rowb + DINNER + h * DSTATE + p];
        Cs[i * 65 + p] = xBC[rowb + DINNER + NH * DSTATE + h * DSTATE + p];
    }
    if (tid < CHUNK) {
        float d = zx[(size_t)(m0 + tid) * DINPROJ + DTOFF + h];
        float sp = (d > 20.f) ? d : log1pf(expf(d));
        cum[tid] = -sp;
    }
    __syncthreads();
    // inclusive scan (Hillis-Steele)
    for (int off = 1; off < CHUNK; off <<= 1) {
        float v = 0.f;
        if (tid < CHUNK && tid >= off) v = cum[tid - off];
        __syncthreads();
        if (tid < CHUNK && tid >= off) cum[tid] += v;
        __syncthreads();
    }
    if (tid < CHUNK) dend[tid] = expf(cum[CHUNK - 1] - cum[tid]);
    __syncthreads();

    int ty = tid >> 4, tx = tid & 15;
    // Phase A: masked decayed scores sc[i][j] = exp(cum_i - cum_j) * dot(C_i, B_j)
    {
        float acc[8][8];
        #pragma unroll
        for (int r = 0; r < 8; r++)
            #pragma unroll
            for (int s = 0; s < 8; s++) acc[r][s] = 0.f;
        int i0 = ty * 8;
        for (int n = 0; n < DSTATE; n++) {
            float cf[8], bf[8];
            #pragma unroll
            for (int r = 0; r < 8; r++) cf[r] = Cs[(i0 + r) * 65 + n];
            #pragma unroll
            for (int s = 0; s < 8; s++) bf[s] = Bs[(tx + 16 * s) * 65 + n];
            #pragma unroll
            for (int r = 0; r < 8; r++)
                #pragma unroll
                for (int s = 0; s < 8; s++) acc[r][s] += cf[r] * bf[s];
        }
        #pragma unroll
        for (int r = 0; r < 8; r++) {
            int i = i0 + r;
            float ci = cum[i];
            #pragma unroll
            for (int s = 0; s < 8; s++) {
                int j = tx + 16 * s;
                sc[i * 129 + j] = (j <= i) ? expf(ci - cum[j]) * acc[r][s] : 0.f;
            }
        }
    }
    __syncthreads();
    // Phase B: y_intra = sc @ x
    {
        float acc[8][4];
        #pragma unroll
        for (int r = 0; r < 8; r++)
            #pragma unroll
            for (int cc = 0; cc < 4; cc++) acc[r][cc] = 0.f;
        int i0 = ty * 8, p0 = tx * 4;
        for (int j = 0; j < CHUNK; j++) {
            float xv[4];
            #pragma unroll
            for (int cc = 0; cc < 4; cc++) xv[cc] = xs[j * 65 + p0 + cc];
            #pragma unroll
            for (int r = 0; r < 8; r++) {
                float sf = sc[(i0 + r) * 129 + j];
                #pragma unroll
                for (int cc = 0; cc < 4; cc++) acc[r][cc] += sf * xv[cc];
            }
        }
        #pragma unroll
        for (int r = 0; r < 8; r++) {
            size_t ybase = (size_t)(m0 + i0 + r) * DINNER + h * HD + p0;
            #pragma unroll
            for (int cc = 0; cc < 4; cc++) y[ybase + cc] = acc[r][cc];
        }
    }
    // Phase C: chunk state S[n][p] = sum_j dend[j] * B[j,n] * x[j,p]
    {
        int n = tid >> 2;
        int p0 = (tid & 3) * 16;
        float acc[16];
        #pragma unroll
        for (int cc = 0; cc < 16; cc++) acc[cc] = 0.f;
        for (int j = 0; j < CHUNK; j++) {
            float w = dend[j] * Bs[j * 65 + n];
            #pragma unroll
            for (int cc = 0; cc < 16; cc++) acc[cc] += w * xs[j * 65 + p0 + cc];
        }
        size_t off = ((size_t)((b * NCHUNK + c) * NH + h)) * (DSTATE * HD) + n * HD + p0;
        #pragma unroll
        for (int cc = 0; cc < 16; cc++) Sg[off + cc] = acc[cc];
        if (tid == 0) Ag[(b * NCHUNK + c) * NH + h] = expf(cum[CHUNK - 1]);
    }
    if (tid < CHUNK)
        cumg[((size_t)((b * NCHUNK + c) * NH + h)) * CHUNK + tid] = cum[tid];
}

// ------------------------------ inter-chunk state recurrence ----------------
__global__ void state_scan_kernel(const float* __restrict__ Sg, const float* __restrict__ Ag,
                                  float* __restrict__ Hp) {
    int b = blockIdx.x / NH, h = blockIdx.x % NH;
    int tid = threadIdx.x;
    float H[16];
    #pragma unroll
    for (int k = 0; k < 16; k++) H[k] = 0.f;
    for (int c = 0; c < NCHUNK; c++) {
        size_t off = ((size_t)((b * NCHUNK + c) * NH + h)) * (DSTATE * HD);
        float Ac = Ag[(b * NCHUNK + c) * NH + h];
        #pragma unroll
        for (int k = 0; k < 16; k++) {
            int e = tid + k * 256;
            Hp[off + e] = H[k];
            H[k] = Ac * H[k] + Sg[off + e];
        }
    }
}

// ------------------------------ y_inter + D*x + gating ---------------------
__global__ void y_inter_kernel(const float* __restrict__ zx, const float* __restrict__ xBC,
                               const float* __restrict__ Hp, const float* __restrict__ cumg,
                               const float* __restrict__ Dvec, const float* __restrict__ zb,
                               float* __restrict__ y) {
    extern __shared__ float sm[];
    float* Cs  = sm;                  // 128*65
    float* xs  = Cs + CHUNK * 65;     // 128*65
    float* Hs  = xs + CHUNK * 65;     // 64*65
    float* cum = Hs + DSTATE * 65;    // 128

    int h = blockIdx.x % NH;
    int c = (blockIdx.x / NH) % NCHUNK;
    int b = blockIdx.x / (NH * NCHUNK);
    int tid = threadIdx.x;
    int m0 = b * LSEQ + c * CHUNK;
    size_t hoff = (size_t)((b * NCHUNK + c) * NH + h);

    for (int idx = tid; idx < CHUNK * HD; idx += 256) {
        int i = idx >> 6, p = idx & 63;
        size_t rowb = (size_t)(m0 + i) * CONVD;
        xs[i * 65 + p] = xBC[rowb + h * HD + p];
        Cs[i * 65 + p] = xBC[rowb + DINNER + NH * DSTATE + h * DSTATE + p];
    }
    for (int idx = tid; idx < DSTATE * HD; idx += 256)
        Hs[(idx >> 6) * 65 + (idx & 63)] = Hp[hoff * (DSTATE * HD) + idx];
    if (tid < CHUNK) cum[tid] = cumg[hoff * CHUNK + tid];
    __syncthreads();

    int i = tid >> 1;
    int p0 = (tid & 1) * 32;
    float acc[32];
    #pragma unroll
    for (int cc = 0; cc < 32; cc++) acc[cc] = 0.f;
    for (int n = 0; n < DSTATE; n++) {
        float cv = Cs[i * 65 + n];
        #pragma unroll
        for (int cc = 0; cc < 32; cc++) acc[cc] += cv * Hs[n * 65 + p0 + cc];
    }
    float e = expf(cum[i]);
    float Dh = Dvec[h];
    int m = m0 + i;
    size_t ybase = (size_t)m * DINNER + h * HD;
    size_t zbase = (size_t)m * DINPROJ + h * HD;
    #pragma unroll
    for (int cc = 0; cc < 32; cc++) {
        int p = p0 + cc;
        float yt = y[ybase + p] + e * acc[cc] + Dh * xs[i * 65 + p];
        float g = zx[zbase + p] + zb[h * HD + p];
        float sg = g / (1.f + expf(-g));
        y[ybase + p] = yt * sg;
    }
}

// ------------------------------ MLP elementwise -----------------------------
__global__ void silu_mul_kernel(float* __restrict__ gate, const float* __restrict__ up,
                                size_t n) {
    size_t i = (size_t)blockIdx.x * blockDim.x + threadIdx.x;
    if (i < n) {
        float g = gate[i];
        gate[i] = (g / (1.f + expf(-g))) * up[i];
    }
}

// ------------------------------ launch --------------------------------------
extern "C" void kernel_launch(void* const* d_in, const int* in_sizes, int n_in,
                              void* d_out, int out_size) {
    const float* hidden     = (const float*)d_in[0];
    const float* in_proj_w  = (const float*)d_in[1];
    const float* z_bias     = (const float*)d_in[2];
    const float* conv_w     = (const float*)d_in[3];
    const float* conv_b     = (const float*)d_in[4];
    const float* Dvec       = (const float*)d_in[5];
    const float* out_proj_w = (const float*)d_in[6];
    const float* norm1_w    = (const float*)d_in[7];
    const float* norm2_w    = (const float*)d_in[8];
    const float* gate_w     = (const float*)d_in[9];
    const float* up_w       = (const float*)d_in[10];
    const float* down_w     = (const float*)d_in[11];
    float* out = (float*)d_out;

    float *h1, *zx, *xbc, *y, *S, *A, *cumg, *Hp, *h2, *h3, *gate, *up;
    cudaGetSymbolAddress((void**)&h1,   g_h1);
    cudaGetSymbolAddress((void**)&zx,   g_zx);
    cudaGetSymbolAddress((void**)&xbc,  g_xBC);
    cudaGetSymbolAddress((void**)&y,    g_y);
    cudaGetSymbolAddress((void**)&S,    g_S);
    cudaGetSymbolAddress((void**)&A,    g_Ac);
    cudaGetSymbolAddress((void**)&cumg, g_cum);
    cudaGetSymbolAddress((void**)&Hp,   g_Hp);
    cudaGetSymbolAddress((void**)&h2,   g_h2);
    cudaGetSymbolAddress((void**)&h3,   g_h3);
    cudaGetSymbolAddress((void**)&gate, g_gate);
    cudaGetSymbolAddress((void**)&up,   g_up);

    const int SMEM_INTRA  = (3 * CHUNK * 65 + CHUNK * 129 + 2 * CHUNK) * sizeof(float);
    const int SMEM_YINTER = (2 * CHUNK * 65 + DSTATE * 65 + CHUNK) * sizeof(float);
    cudaFuncSetAttribute(ssd_intra_kernel, cudaFuncAttributeMaxDynamicSharedMemorySize, SMEM_INTRA);
    cudaFuncSetAttribute(y_inter_kernel,  cudaFuncAttributeMaxDynamicSharedMemorySize, SMEM_YINTER);

    // 1) rmsnorm 1
    rmsnorm_kernel<<<MTOK, 256>>>(hidden, norm1_w, h1);
    // 2) in_proj: zx = h1 @ in_proj_w^T   [4096 x 8224]
    sgemm_nt_kernel<<<dim3((DINPROJ + 127) / 128, MTOK / 128), 256>>>(
        h1, in_proj_w, nullptr, zx, MTOK, DINPROJ, DMODEL);
    // 3) causal depthwise conv over xBC slice
    conv1d_kernel<<<(int)(((size_t)MTOK * CONVD + 255) / 256), 256>>>(zx, conv_w, conv_b, xbc);
    // 4) SSD intra-chunk (y_intra, S, A, cum)
    ssd_intra_kernel<<<BATCH * NCHUNK * NH, 256, SMEM_INTRA>>>(zx, xbc, y, S, A, cumg);
    // 5) inter-chunk state recurrence
    state_scan_kernel<<<BATCH * NH, 256>>>(S, A, Hp);
    // 6) y_inter + D*x + silu(z) gating (in-place on y)
    y_inter_kernel<<<BATCH * NCHUNK * NH, 256, SMEM_YINTER>>>(zx, xbc, Hp, cumg, Dvec, z_bias, y);
    // 7) out_proj + residual: h2 = y @ out_proj_w^T + hidden
    sgemm_nt_kernel<<<dim3(DMODEL / 128, MTOK / 128), 256>>>(
        y, out_proj_w, hidden, h2, MTOK, DMODEL, DINNER);
    // 8) rmsnorm 2
    rmsnorm_kernel<<<MTOK, 256>>>(h2, norm2_w, h3);
    // 9) MLP gate / up
    sgemm_nt_kernel<<<dim3(DFF / 128, MTOK / 128), 256>>>(
        h3, gate_w, nullptr, gate, MTOK, DFF, DMODEL);
    sgemm_nt_kernel<<<dim3(DFF / 128, MTOK / 128), 256>>>(
        h3, up_w, nullptr, up, MTOK, DFF, DMODEL);
    // 10) act = silu(gate) * up (in-place on gate)
    silu_mul_kernel<<<(int)(((size_t)MTOK * DFF + 255) / 256), 256>>>(
        gate, up, (size_t)MTOK * DFF);
    // 11) down + residual: out = act @ down_w^T + h2
    sgemm_nt_kernel<<<dim3(DMODEL / 128, MTOK / 128), 256>>>(
        gate, down_w, h2, out, MTOK, DMODEL, DFF);
}

// round 8
// speedup vs baseline: 1.0482x; 1.0482x over previous
#include <cuda_runtime.h>
#include <math.h>

#define BATCH   2
#define LSEQ    2048
#define MTOK    (BATCH*LSEQ)          // 4096
#define DMODEL  2048
#define DINNER  2048
#define NH      32
#define DSTATE  64
#define HD      64
#define CHUNK   128
#define NCHUNK  (LSEQ/CHUNK)          // 16
#define DFF     8192
#define CONVD   (DINNER + 2*NH*DSTATE)          // 6144
#define DINPROJ (2*DINNER + 2*NH*DSTATE + NH)   // 8224
#define DTOFF   (DINNER + CONVD)                // 8192

// ------------------------- scratch (device globals, no allocs) -------------
__device__ float g_h1  [(size_t)MTOK*DMODEL];
__device__ float g_zx  [(size_t)MTOK*DINPROJ];
__device__ float g_xBC [(size_t)MTOK*CONVD];
__device__ float g_y   [(size_t)MTOK*DINNER];
__device__ float g_S   [(size_t)BATCH*NCHUNK*NH*DSTATE*HD];
__device__ float g_Ac  [(size_t)BATCH*NCHUNK*NH];
__device__ float g_cum [(size_t)BATCH*NCHUNK*NH*CHUNK];
__device__ float g_Hp  [(size_t)BATCH*NCHUNK*NH*DSTATE*HD];
__device__ float g_h2  [(size_t)MTOK*DMODEL];
__device__ float g_h3  [(size_t)MTOK*DMODEL];
__device__ float g_gate[(size_t)MTOK*DFF];
__device__ float g_up  [(size_t)MTOK*DFF];

// ------------------------------ rmsnorm ------------------------------------
__global__ void rmsnorm_kernel(const float* __restrict__ x, const float* __restrict__ w,
                               float* __restrict__ y) {
    int row = blockIdx.x;
    const float* xr = x + (size_t)row * DMODEL;
    float ss = 0.f;
    for (int c = threadIdx.x; c < DMODEL; c += 256) { float v = xr[c]; ss += v * v; }
    #pragma unroll
    for (int off = 16; off; off >>= 1) ss += __shfl_xor_sync(0xffffffffu, ss, off);
    __shared__ float red[8];
    if ((threadIdx.x & 31) == 0) red[threadIdx.x >> 5] = ss;
    __syncthreads();
    if (threadIdx.x < 8) {
        float v = red[threadIdx.x];
        #pragma unroll
        for (int off = 4; off; off >>= 1) v += __shfl_xor_sync(0xffu, v, off);
        if (threadIdx.x == 0) red[0] = v;
    }
    __syncthreads();
    float inv = rsqrtf(red[0] / (float)DMODEL + 1e-5f);
    float* yr = y + (size_t)row * DMODEL;
    for (int c = threadIdx.x; c < DMODEL; c += 256) yr[c] = w[c] * xr[c] * inv;
}

// ------------------------------ SGEMM (C = A * W^T [+ res]) ----------------
// A: [M,K] row-major, W: [N,K] row-major, C: [M,N]. 128x128 tile, BK=16,
// 256 threads, 8x8 per thread. M % 128 == 0, K % 16 == 0, N guarded.
__global__ void sgemm_nt_kernel(const float* __restrict__ A, const float* __restrict__ W,
                                const float* __restrict__ res, float* __restrict__ C,
                                int M, int N, int K) {
    __shared__ float As[16][129];
    __shared__ float Ws[16][129];
    int tid = threadIdx.x;
    int bm = blockIdx.y * 128, bn = blockIdx.x * 128;
    int ty = tid >> 4, tx = tid & 15;
    int lr = tid >> 2;            // 0..63
    int lc = (tid & 3) * 4;       // 0,4,8,12

    float acc[8][8];
    #pragma unroll
    for (int r = 0; r < 8; r++)
        #pragma unroll
        for (int s = 0; s < 8; s++) acc[r][s] = 0.f;

    for (int k0 = 0; k0 < K; k0 += 16) {
        #pragma unroll
        for (int pass = 0; pass < 2; pass++) {
            int r = lr + pass * 64;
            float4 av = *(const float4*)(A + (size_t)(bm + r) * K + k0 + lc);
            As[lc + 0][r] = av.x; As[lc + 1][r] = av.y;
            As[lc + 2][r] = av.z; As[lc + 3][r] = av.w;
            int n = bn + r;
            float4 wv = make_float4(0.f, 0.f, 0.f, 0.f);
            if (n < N) wv = *(const float4*)(W + (size_t)n * K + k0 + lc);
            Ws[lc + 0][r] = wv.x; Ws[lc + 1][r] = wv.y;
            Ws[lc + 2][r] = wv.z; Ws[lc + 3][r] = wv.w;
        }
        __syncthreads();
        #pragma unroll
        for (int kk = 0; kk < 16; kk++) {
            float af[8], bf[8];
            #pragma unroll
            for (int r = 0; r < 8; r++) af[r] = As[kk][ty * 8 + r];
            #pragma unroll
            for (int s = 0; s < 8; s++) bf[s] = Ws[kk][tx * 8 + s];
            #pragma unroll
            for (int r = 0; r < 8; r++)
                #pragma unroll
                for (int s = 0; s < 8; s++) acc[r][s] += af[r] * bf[s];
        }
        __syncthreads();
    }
    #pragma unroll
    for (int r = 0; r < 8; r++) {
        int m = bm + ty * 8 + r;
        #pragma unroll
        for (int s = 0; s < 8; s++) {
            int n = bn + tx * 8 + s;
            if (n < N) {
                float v = acc[r][s];
                if (res) v += res[(size_t)m * N + n];
                C[(size_t)m * N + n] = v;
            }
        }
    }
}

// ------------------------------ causal depthwise conv ----------------------
__global__ void conv1d_kernel(const float* __restrict__ zx, const float* __restrict__ cw,
                              const float* __restrict__ cb, float* __restrict__ xBC) {
    size_t idx = (size_t)blockIdx.x * blockDim.x + threadIdx.x;
    if (idx >= (size_t)MTOK * CONVD) return;
    int c = (int)(idx % CONVD);
    int m = (int)(idx / CONVD);
    int t = m & (LSEQ - 1);           // position within sequence
    float acc = cb[c];
    #pragma unroll
    for (int j = 0; j < 4; j++) {
        int tt = t - 3 + j;
        if (tt >= 0)
            acc += cw[c * 4 + j] * zx[(size_t)(m - 3 + j) * DINPROJ + DINNER + c];
    }
    xBC[idx] = acc;
}

// ------------------------------ SSD intra-chunk ----------------------------
// one block per (b, chunk, head). Computes y_intra, chunk state S, A_chunk, cum.
__global__ void ssd_intra_kernel(const float* __restrict__ zx, const float* __restrict__ xBC,
                                 float* __restrict__ y, float* __restrict__ Sg,
                                 float* __restrict__ Ag, float* __restrict__ cumg) {
    extern __shared__ float sm[];
    float* xs   = sm;                       // 128*65
    float* Bs   = xs + CHUNK * 65;          // 128*65
    float* Cs   = Bs + CHUNK * 65;          // 128*65
    float* sc   = Cs + CHUNK * 65;          // 128*129
    float* cum  = sc + CHUNK * 129;         // 128
    float* dend = cum + CHUNK;              // 128

    int h = blockIdx.x % NH;
    int c = (blockIdx.x / NH) % NCHUNK;
    int b = blockIdx.x / (NH * NCHUNK);
    int tid = threadIdx.x;
    int m0 = b * LSEQ + c * CHUNK;

    for (int idx = tid; idx < CHUNK * HD; idx += 256) {
        int i = idx >> 6, p = idx & 63;
        size_t rowb = (size_t)(m0 + i) * CONVD;
        xs[i * 65 + p] = xBC[rowb + h * HD + p];
        Bs[i * 65 + p] = xBC[rowb + DINNER + h * DSTATE + p];
        Cs[i * 65 + p] = xBC[rowb + DINNER + NH * DSTATE + h * DSTATE + p];
    }
    if (tid < CHUNK) {
        float d = zx[(size_t)(m0 + tid) * DINPROJ + DTOFF + h];
        float sp = (d > 20.f) ? d : log1pf(expf(d));
        cum[tid] = -sp;
    }
    __syncthreads();
    // inclusive scan (Hillis-Steele)
    for (int off = 1; off < CHUNK; off <<= 1) {
        float v = 0.f;
        if (tid < CHUNK && tid >= off) v = cum[tid - off];
        __syncthreads();
        if (tid < CHUNK && tid >= off) cum[tid] += v;
        __syncthreads();
    }
    if (tid < CHUNK) dend[tid] = expf(cum[CHUNK - 1] - cum[tid]);
    __syncthreads();

    int ty = tid >> 4, tx = tid & 15;
    // Phase A: masked decayed scores sc[i][j] = exp(cum_i - cum_j) * dot(C_i, B_j)
    {
        float acc[8][8];
        #pragma unroll
        for (int r = 0; r < 8; r++)
            #pragma unroll
            for (int s = 0; s < 8; s++) acc[r][s] = 0.f;
        int i0 = ty * 8;
        for (int n = 0; n < DSTATE; n++) {
            float cf[8], bf[8];
            #pragma unroll
            for (int r = 0; r < 8; r++) cf[r] = Cs[(i0 + r) * 65 + n];
            #pragma unroll
            for (int s = 0; s < 8; s++) bf[s] = Bs[(tx + 16 * s) * 65 + n];
            #pragma unroll
            for (int r = 0; r < 8; r++)
                #pragma unroll
                for (int s = 0; s < 8; s++) acc[r][s] += cf[r] * bf[s];
        }
        #pragma unroll
        for (int r = 0; r < 8; r++) {
            int i = i0 + r;
            float ci = cum[i];
            #pragma unroll
            for (int s = 0; s < 8; s++) {
                int j = tx + 16 * s;
                sc[i * 129 + j] = (j <= i) ? expf(ci - cum[j]) * acc[r][s] : 0.f;
            }
        }
    }
    __syncthreads();
    // Phase B: y_intra = sc @ x
    {
        float acc[8][4];
        #pragma unroll
        for (int r = 0; r < 8; r++)
            #pragma unroll
            for (int cc = 0; cc < 4; cc++) acc[r][cc] = 0.f;
        int i0 = ty * 8, p0 = tx * 4;
        for (int j = 0; j < CHUNK; j++) {
            float xv[4];
            #pragma unroll
            for (int cc = 0; cc < 4; cc++) xv[cc] = xs[j * 65 + p0 + cc];
            #pragma unroll
            for (int r = 0; r < 8; r++) {
                float sf = sc[(i0 + r) * 129 + j];
                #pragma unroll
                for (int cc = 0; cc < 4; cc++) acc[r][cc] += sf * xv[cc];
            }
        }
        #pragma unroll
        for (int r = 0; r < 8; r++) {
            size_t ybase = (size_t)(m0 + i0 + r) * DINNER + h * HD + p0;
            #pragma unroll
            for (int cc = 0; cc < 4; cc++) y[ybase + cc] = acc[r][cc];
        }
    }
    // Phase C: chunk state S[n][p] = sum_j dend[j] * B[j,n] * x[j,p]
    {
        int n = tid >> 2;
        int p0 = (tid & 3) * 16;
        float acc[16];
        #pragma unroll
        for (int cc = 0; cc < 16; cc++) acc[cc] = 0.f;
        for (int j = 0; j < CHUNK; j++) {
            float w = dend[j] * Bs[j * 65 + n];
            #pragma unroll
            for (int cc = 0; cc < 16; cc++) acc[cc] += w * xs[j * 65 + p0 + cc];
        }
        size_t off = ((size_t)((b * NCHUNK + c) * NH + h)) * (DSTATE * HD) + n * HD + p0;
        #pragma unroll
        for (int cc = 0; cc < 16; cc++) Sg[off + cc] = acc[cc];
        if (tid == 0) Ag[(b * NCHUNK + c) * NH + h] = expf(cum[CHUNK - 1]);
    }
    if (tid < CHUNK)
        cumg[((size_t)((b * NCHUNK + c) * NH + h)) * CHUNK + tid] = cum[tid];
}

// ------------------------------ inter-chunk state recurrence ----------------
__global__ void state_scan_kernel(const float* __restrict__ Sg, const float* __restrict__ Ag,
                                  float* __restrict__ Hp) {
    int b = blockIdx.x / NH, h = blockIdx.x % NH;
    int tid = threadIdx.x;
    float H[16];
    #pragma unroll
    for (int k = 0; k < 16; k++) H[k] = 0.f;
    for (int c = 0; c < NCHUNK; c++) {
        size_t off = ((size_t)((b * NCHUNK + c) * NH + h)) * (DSTATE * HD);
        float Ac = Ag[(b * NCHUNK + c) * NH + h];
        #pragma unroll
        for (int k = 0; k < 16; k++) {
            int e = tid + k * 256;
            Hp[off + e] = H[k];
            H[k] = Ac * H[k] + Sg[off + e];
        }
    }
}

// ------------------------------ y_inter + D*x + gating ---------------------
__global__ void y_inter_kernel(const float* __restrict__ zx, const float* __restrict__ xBC,
                               const float* __restrict__ Hp, const float* __restrict__ cumg,
                               const float* __restrict__ Dvec, const float* __restrict__ zb,
                               float* __restrict__ y) {
    extern __shared__ float sm[];
    float* Cs  = sm;                  // 128*65
    float* xs  = Cs + CHUNK * 65;     // 128*65
    float* Hs  = xs + CHUNK * 65;     // 64*65
    float* cum = Hs + DSTATE * 65;    // 128

    int h = blockIdx.x % NH;
    int c = (blockIdx.x / NH) % NCHUNK;
    int b = blockIdx.x / (NH * NCHUNK);
    int tid = threadIdx.x;
    int m0 = b * LSEQ + c * CHUNK;
    size_t hoff = (size_t)((b * NCHUNK + c) * NH + h);

    for (int idx = tid; idx < CHUNK * HD; idx += 256) {
        int i = idx >> 6, p = idx & 63;
        size_t rowb = (size_t)(m0 + i) * CONVD;
        xs[i * 65 + p] = xBC[rowb + h * HD + p];
        Cs[i * 65 + p] = xBC[rowb + DINNER + NH * DSTATE + h * DSTATE + p];
    }
    for (int idx = tid; idx < DSTATE * HD; idx += 256)
        Hs[(idx >> 6) * 65 + (idx & 63)] = Hp[hoff * (DSTATE * HD) + idx];
    if (tid < CHUNK) cum[tid] = cumg[hoff * CHUNK + tid];
    __syncthreads();

    int i = tid >> 1;
    int p0 = (tid & 1) * 32;
    float acc[32];
    #pragma unroll
    for (int cc = 0; cc < 32; cc++) acc[cc] = 0.f;
    for (int n = 0; n < DSTATE; n++) {
        float cv = Cs[i * 65 + n];
        #pragma unroll
        for (int cc = 0; cc < 32; cc++) acc[cc] += cv * Hs[n * 65 + p0 + cc];
    }
    float e = expf(cum[i]);
    float Dh = Dvec[h];
    int m = m0 + i;
    size_t ybase = (size_t)m * DINNER + h * HD;
    size_t zbase = (size_t)m * DINPROJ + h * HD;
    #pragma unroll
    for (int cc = 0; cc < 32; cc++) {
        int p = p0 + cc;
        float yt = y[ybase + p] + e * acc[cc] + Dh * xs[i * 65 + p];
        float g = zx[zbase + p] + zb[h * HD + p];
        float sg = g / (1.f + expf(-g));
        y[ybase + p] = yt * sg;
    }
}

// ------------------------------ MLP elementwise -----------------------------
__global__ void silu_mul_kernel(float* __restrict__ gate, const float* __restrict__ up,
                                size_t n) {
    size_t i = (size_t)blockIdx.x * blockDim.x + threadIdx.x;
    if (i < n) {
        float g = gate[i];
        gate[i] = (g / (1.f + expf(-g))) * up[i];
    }
}

// ------------------------------ launch --------------------------------------
extern "C" void kernel_launch(void* const* d_in, const int* in_sizes, int n_in,
                              void* d_out, int out_size) {
    const float* hidden     = (const float*)d_in[0];
    const float* in_proj_w  = (const float*)d_in[1];
    const float* z_bias     = (const float*)d_in[2];
    const float* conv_w     = (const float*)d_in[3];
    const float* conv_b     = (const float*)d_in[4];
    const float* Dvec       = (const float*)d_in[5];
    const float* out_proj_w = (const float*)d_in[6];
    const float* norm1_w    = (const float*)d_in[7];
    const float* norm2_w    = (const float*)d_in[8];
    const float* gate_w     = (const float*)d_in[9];
    const float* up_w       = (const float*)d_in[10];
    const float* down_w     = (const float*)d_in[11];
    float* out = (float*)d_out;

    float *h1, *zx, *xbc, *y, *S, *A, *cumg, *Hp, *h2, *h3, *gate, *up;
    cudaGetSymbolAddress((void**)&h1,   g_h1);
    cudaGetSymbolAddress((void**)&zx,   g_zx);
    cudaGetSymbolAddress((void**)&xbc,  g_xBC);
    cudaGetSymbolAddress((void**)&y,    g_y);
    cudaGetSymbolAddress((void**)&S,    g_S);
    cudaGetSymbolAddress((void**)&A,    g_Ac);
    cudaGetSymbolAddress((void**)&cumg, g_cum);
    cudaGetSymbolAddress((void**)&Hp,   g_Hp);
    cudaGetSymbolAddress((void**)&h2,   g_h2);
    cudaGetSymbolAddress((void**)&h3,   g_h3);
    cudaGetSymbolAddress((void**)&gate, g_gate);
    cudaGetSymbolAddress((void**)&up,   g_up);

    const int SMEM_INTRA  = (3 * CHUNK * 65 + CHUNK * 129 + 2 * CHUNK) * sizeof(float);
    const int SMEM_YINTER = (2 * CHUNK * 65 + DSTATE * 65 + CHUNK) * sizeof(float);
    cudaFuncSetAttribute(ssd_intra_kernel, cudaFuncAttributeMaxDynamicSharedMemorySize, SMEM_INTRA);
    cudaFuncSetAttribute(y_inter_kernel,  cudaFuncAttributeMaxDynamicSharedMemorySize, SMEM_YINTER);

    // 1) rmsnorm 1
    rmsnorm_kernel<<<MTOK, 256>>>(hidden, norm1_w, h1);
    // 2) in_proj: zx = h1 @ in_proj_w^T   [4096 x 8224]
    sgemm_nt_kernel<<<dim3((DINPROJ + 127) / 128, MTOK / 128), 256>>>(
        h1, in_proj_w, nullptr, zx, MTOK, DINPROJ, DMODEL);
    // 3) causal depthwise conv over xBC slice
    conv1d_kernel<<<(int)(((size_t)MTOK * CONVD + 255) / 256), 256>>>(zx, conv_w, conv_b, xbc);
    // 4) SSD intra-chunk (y_intra, S, A, cum)
    ssd_intra_kernel<<<BATCH * NCHUNK * NH, 256, SMEM_INTRA>>>(zx, xbc, y, S, A, cumg);
    // 5) inter-chunk state recurrence
    state_scan_kernel<<<BATCH * NH, 256>>>(S, A, Hp);
    // 6) y_inter + D*x + silu(z) gating (in-place on y)
    y_inter_kernel<<<BATCH * NCHUNK * NH, 256, SMEM_YINTER>>>(zx, xbc, Hp, cumg, Dvec, z_bias, y);
    // 7) out_proj + residual: h2 = y @ out_proj_w^T + hidden
    sgemm_nt_kernel<<<dim3(DMODEL / 128, MTOK / 128), 256>>>(
        y, out_proj_w, hidden, h2, MTOK, DMODEL, DINNER);
    // 8) rmsnorm 2
    rmsnorm_kernel<<<MTOK, 256>>>(h2, norm2_w, h3);
    // 9) MLP gate / up
    sgemm_nt_kernel<<<dim3(DFF / 128, MTOK / 128), 256>>>(
        h3, gate_w, nullptr, gate, MTOK, DFF, DMODEL);
    sgemm_nt_kernel<<<dim3(DFF / 128, MTOK / 128), 256>>>(
        h3, up_w, nullptr, up, MTOK, DFF, DMODEL);
    // 10) act = silu(gate) * up (in-place on gate)
    silu_mul_kernel<<<(int)(((size_t)MTOK * DFF + 255) / 256), 256>>>(
        gate, up, (size_t)MTOK * DFF);
    // 11) down + residual: out = act @ down_w^T + h2
    sgemm_nt_kernel<<<dim3(DMODEL / 128, MTOK / 128), 256>>>(
        gate, down_w, h2, out, MTOK, DMODEL, DFF);
}

// round 9
// speedup vs baseline: 3.7051x; 3.5346x over previous
#include <cuda_runtime.h>
#include <math.h>
#include <stdint.h>

#define BATCH   2
#define LSEQ    2048
#define MTOK    (BATCH*LSEQ)          // 4096
#define DMODEL  2048
#define DINNER  2048
#define NH      32
#define DSTATE  64
#define HD      64
#define CHUNK   128
#define NCHUNK  (LSEQ/CHUNK)          // 16
#define DFF     8192
#define CONVD   (DINNER + 2*NH*DSTATE)          // 6144
#define DINPROJ (2*DINNER + 2*NH*DSTATE + NH)   // 8224
#define DTOFF   (DINNER + CONVD)                // 8192

// ------------------------- scratch (device globals, no allocs) -------------
__device__ float g_h1  [(size_t)MTOK*DMODEL];
__device__ float g_zx  [(size_t)MTOK*DINPROJ];
__device__ float g_xBC [(size_t)MTOK*CONVD];
__device__ float g_y   [(size_t)MTOK*DINNER];
__device__ float g_S   [(size_t)BATCH*NCHUNK*NH*DSTATE*HD];
__device__ float g_Ac  [(size_t)BATCH*NCHUNK*NH];
__device__ float g_cum [(size_t)BATCH*NCHUNK*NH*CHUNK];
__device__ float g_Hp  [(size_t)BATCH*NCHUNK*NH*DSTATE*HD];
__device__ float g_h2  [(size_t)MTOK*DMODEL];
__device__ float g_h3  [(size_t)MTOK*DMODEL];
__device__ float g_gate[(size_t)MTOK*DFF];
__device__ float g_up  [(size_t)MTOK*DFF];
// tf32-rounded weight copies
__device__ float g_wip [(size_t)DINPROJ*DMODEL];
__device__ float g_wop [(size_t)DMODEL*DINNER];
__device__ float g_wg  [(size_t)DFF*DMODEL];
__device__ float g_wu  [(size_t)DFF*DMODEL];
__device__ float g_wd  [(size_t)DMODEL*DFF];

// ------------------------------ helpers ------------------------------------
__device__ __forceinline__ float tf32r(float x) {
    uint32_t u;
    asm("cvt.rna.tf32.f32 %0, %1;" : "=r"(u) : "f"(x));
    return __uint_as_float(u);
}
__device__ __forceinline__ uint32_t smem_u32(const void* p) {
    uint32_t r;
    asm("{ .reg .u64 t; cvta.to.shared.u64 t, %1; cvt.u32.u64 %0, t; }" : "=r"(r) : "l"(p));
    return r;
}
__device__ __forceinline__ void cpa16(uint32_t dst, const void* src, int bytes) {
    asm volatile("cp.async.cg.shared.global [%0], [%1], 16, %2;\n"
                 :: "r"(dst), "l"(src), "r"(bytes));
}
__device__ __forceinline__ void cpa_commit() { asm volatile("cp.async.commit_group;\n"); }
__device__ __forceinline__ void cpa_wait0()  { asm volatile("cp.async.wait_group 0;\n"); }

// round fp32 buffer to tf32 (float4 granularity; all sizes divisible by 4)
__global__ void round_tf32_kernel(const float* __restrict__ in, float* __restrict__ out,
                                  int n4) {
    int i = blockIdx.x * blockDim.x + threadIdx.x;
    if (i < n4) {
        float4 v = ((const float4*)in)[i];
        v.x = tf32r(v.x); v.y = tf32r(v.y); v.z = tf32r(v.z); v.w = tf32r(v.w);
        ((float4*)out)[i] = v;
    }
}

// ------------------------------ rmsnorm (tf32-rounded output) ---------------
__global__ void rmsnorm_kernel(const float* __restrict__ x, const float* __restrict__ w,
                               float* __restrict__ y) {
    int row = blockIdx.x;
    const float* xr = x + (size_t)row * DMODEL;
    float ss = 0.f;
    for (int c = threadIdx.x; c < DMODEL; c += 256) { float v = xr[c]; ss += v * v; }
    #pragma unroll
    for (int off = 16; off; off >>= 1) ss += __shfl_xor_sync(0xffffffffu, ss, off);
    __shared__ float red[8];
    if ((threadIdx.x & 31) == 0) red[threadIdx.x >> 5] = ss;
    __syncthreads();
    if (threadIdx.x < 8) {
        float v = red[threadIdx.x];
        #pragma unroll
        for (int off = 4; off; off >>= 1) v += __shfl_xor_sync(0xffu, v, off);
        if (threadIdx.x == 0) red[0] = v;
    }
    __syncthreads();
    float inv = rsqrtf(red[0] / (float)DMODEL + 1e-5f);
    float* yr = y + (size_t)row * DMODEL;
    for (int c = threadIdx.x; c < DMODEL; c += 256) yr[c] = tf32r(w[c] * xr[c] * inv);
}

// ------------------------------ TF32 tensor-core GEMM -----------------------
// C = A * W^T (+ res). A:[M,K], W:[N,K] row-major, both pre-rounded to tf32.
// 128x128x32 CTA tile, 8 warps of 64x32, mma.sync.m16n8k8.tf32, cp.async x2 buf.
#define BKP 36   // smem row stride (floats) -> conflict-free fragment LDS

__global__ __launch_bounds__(256) void tf32_gemm_kernel(
        const float* __restrict__ A, const float* __restrict__ W,
        const float* __restrict__ res, float* __restrict__ C,
        int M, int N, int K) {
    extern __shared__ float sm[];
    float* As = sm;                        // 2 * 128 * BKP
    float* Ws = sm + 2 * 128 * BKP;        // 2 * 128 * BKP
    const uint32_t as_u = smem_u32(As);
    const uint32_t ws_u = smem_u32(Ws);

    int tid = threadIdx.x;
    int bm = blockIdx.y * 128, bn = blockIdx.x * 128;
    int lane = tid & 31, warp = tid >> 5;
    int wm = (warp >> 2) * 64;       // warp row offset within CTA tile
    int wn = (warp & 3) * 32;        // warp col offset
    int grp = lane >> 2, tig = lane & 3;

    float c[4][4][4];
    #pragma unroll
    for (int mt = 0; mt < 4; mt++)
        #pragma unroll
        for (int nt = 0; nt < 4; nt++)
            #pragma unroll
            for (int e = 0; e < 4; e++) c[mt][nt][e] = 0.f;

    const int ldrow = tid >> 3;        // 0..31 combined with iter below
    const int ldc4  = (tid & 7) * 4;   // 0..28

    auto load_tile = [&](int t, int which) {
        int kb = t * 32;
        uint32_t ab = as_u + (uint32_t)which * 128 * BKP * 4;
        uint32_t wb = ws_u + (uint32_t)which * 128 * BKP * 4;
        #pragma unroll
        for (int i = 0; i < 4; i++) {
            int row = ldrow + i * 32;
            cpa16(ab + (row * BKP + ldc4) * 4,
                  A + (size_t)(bm + row) * K + kb + ldc4, 16);
            int n = bn + row;
            int nn = n < N ? n : (N - 1);
            cpa16(wb + (row * BKP + ldc4) * 4,
                  W + (size_t)nn * K + kb + ldc4, n < N ? 16 : 0);
        }
    };

    int ntiles = K / 32;
    load_tile(0, 0);
    cpa_commit();
    int buf = 0;
    for (int t = 0; t < ntiles; t++) {
        cpa_wait0();
        __syncthreads();
        if (t + 1 < ntiles) { load_tile(t + 1, buf ^ 1); cpa_commit(); }
        const float* Ab = As + buf * 128 * BKP;
        const float* Wb = Ws + buf * 128 * BKP;
        #pragma unroll
        for (int ks = 0; ks < 4; ks++) {
            int k = ks * 8;
            uint32_t af[4][4], bf[4][2];
            #pragma unroll
            for (int mt = 0; mt < 4; mt++) {
                const float* p = Ab + (wm + mt * 16 + grp) * BKP + k + tig;
                af[mt][0] = __float_as_uint(p[0]);
                af[mt][1] = __float_as_uint(p[8 * BKP]);
                af[mt][2] = __float_as_uint(p[4]);
                af[mt][3] = __float_as_uint(p[8 * BKP + 4]);
            }
            #pragma unroll
            for (int nt = 0; nt < 4; nt++) {
                const float* p = Wb + (wn + nt * 8 + grp) * BKP + k + tig;
                bf[nt][0] = __float_as_uint(p[0]);
                bf[nt][1] = __float_as_uint(p[4]);
            }
            #pragma unroll
            for (int mt = 0; mt < 4; mt++)
                #pragma unroll
                for (int nt = 0; nt < 4; nt++) {
                    asm volatile(
                        "mma.sync.aligned.m16n8k8.row.col.f32.tf32.tf32.f32 "
                        "{%0,%1,%2,%3}, {%4,%5,%6,%7}, {%8,%9}, {%0,%1,%2,%3};\n"
                        : "+f"(c[mt][nt][0]), "+f"(c[mt][nt][1]),
                          "+f"(c[mt][nt][2]), "+f"(c[mt][nt][3])
                        : "r"(af[mt][0]), "r"(af[mt][1]), "r"(af[mt][2]), "r"(af[mt][3]),
                          "r"(bf[nt][0]), "r"(bf[nt][1]));
                }
        }
        __syncthreads();
        buf ^= 1;
    }

    // epilogue
    #pragma unroll
    for (int mt = 0; mt < 4; mt++) {
        int r0 = bm + wm + mt * 16 + grp;
        #pragma unroll
        for (int nt = 0; nt < 4; nt++) {
            int col = bn + wn + nt * 8 + 2 * tig;
            if (col < N) {
                float v0 = c[mt][nt][0], v1 = c[mt][nt][1];
                float v2 = c[mt][nt][2], v3 = c[mt][nt][3];
                size_t o0 = (size_t)r0 * N + col;
                size_t o1 = (size_t)(r0 + 8) * N + col;
                if (res) {
                    v0 += res[o0]; v1 += res[o0 + 1];
                    v2 += res[o1]; v3 += res[o1 + 1];
                }
                *(float2*)(C + o0) = make_float2(v0, v1);
                *(float2*)(C + o1) = make_float2(v2, v3);
            }
        }
    }
}

// ------------------------------ causal depthwise conv ----------------------
__global__ void conv1d_kernel(const float* __restrict__ zx, const float* __restrict__ cw,
                              const float* __restrict__ cb, float* __restrict__ xBC) {
    size_t idx = (size_t)blockIdx.x * blockDim.x + threadIdx.x;
    if (idx >= (size_t)MTOK * CONVD) return;
    int c = (int)(idx % CONVD);
    int m = (int)(idx / CONVD);
    int t = m & (LSEQ - 1);
    float acc = cb[c];
    #pragma unroll
    for (int j = 0; j < 4; j++) {
        int tt = t - 3 + j;
        if (tt >= 0)
            acc += cw[c * 4 + j] * zx[(size_t)(m - 3 + j) * DINPROJ + DINNER + c];
    }
    xBC[idx] = acc;
}

// ------------------------------ SSD intra-chunk ----------------------------
__global__ void ssd_intra_kernel(const float* __restrict__ zx, const float* __restrict__ xBC,
                                 float* __restrict__ y, float* __restrict__ Sg,
                                 float* __restrict__ Ag, float* __restrict__ cumg) {
    extern __shared__ float sm[];
    float* xs   = sm;                       // 128*65
    float* Bs   = xs + CHUNK * 65;          // 128*65
    float* Cs   = Bs + CHUNK * 65;          // 128*65
    float* sc   = Cs + CHUNK * 65;          // 128*129
    float* cum  = sc + CHUNK * 129;         // 128
    float* dend = cum + CHUNK;              // 128

    int h = blockIdx.x % NH;
    int c = (blockIdx.x / NH) % NCHUNK;
    int b = blockIdx.x / (NH * NCHUNK);
    int tid = threadIdx.x;
    int m0 = b * LSEQ + c * CHUNK;

    for (int idx = tid; idx < CHUNK * HD; idx += 256) {
        int i = idx >> 6, p = idx & 63;
        size_t rowb = (size_t)(m0 + i) * CONVD;
        xs[i * 65 + p] = xBC[rowb + h * HD + p];
        Bs[i * 65 + p] = xBC[rowb + DINNER + h * DSTATE + p];
        Cs[i * 65 + p] = xBC[rowb + DINNER + NH * DSTATE + h * DSTATE + p];
    }
    if (tid < CHUNK) {
        float d = zx[(size_t)(m0 + tid) * DINPROJ + DTOFF + h];
        float sp = (d > 20.f) ? d : log1pf(expf(d));
        cum[tid] = -sp;
    }
    __syncthreads();
    for (int off = 1; off < CHUNK; off <<= 1) {
        float v = 0.f;
        if (tid < CHUNK && tid >= off) v = cum[tid - off];
        __syncthreads();
        if (tid < CHUNK && tid >= off) cum[tid] += v;
        __syncthreads();
    }
    if (tid < CHUNK) dend[tid] = expf(cum[CHUNK - 1] - cum[tid]);
    __syncthreads();

    int ty = tid >> 4, tx = tid & 15;
    {
        float acc[8][8];
        #pragma unroll
        for (int r = 0; r < 8; r++)
            #pragma unroll
            for (int s = 0; s < 8; s++) acc[r][s] = 0.f;
        int i0 = ty * 8;
        for (int n = 0; n < DSTATE; n++) {
            float cf[8], bf[8];
            #pragma unroll
            for (int r = 0; r < 8; r++) cf[r] = Cs[(i0 + r) * 65 + n];
            #pragma unroll
            for (int s = 0; s < 8; s++) bf[s] = Bs[(tx + 16 * s) * 65 + n];
            #pragma unroll
            for (int r = 0; r < 8; r++)
                #pragma unroll
                for (int s = 0; s < 8; s++) acc[r][s] += cf[r] * bf[s];
        }
        #pragma unroll
        for (int r = 0; r < 8; r++) {
            int i = i0 + r;
            float ci = cum[i];
            #pragma unroll
            for (int s = 0; s < 8; s++) {
                int j = tx + 16 * s;
                sc[i * 129 + j] = (j <= i) ? expf(ci - cum[j]) * acc[r][s] : 0.f;
            }
        }
    }
    __syncthreads();
    {
        float acc[8][4];
        #pragma unroll
        for (int r = 0; r < 8; r++)
            #pragma unroll
            for (int cc = 0; cc < 4; cc++) acc[r][cc] = 0.f;
        int i0 = ty * 8, p0 = tx * 4;
        for (int j = 0; j < CHUNK; j++) {
            float xv[4];
            #pragma unroll
            for (int cc = 0; cc < 4; cc++) xv[cc] = xs[j * 65 + p0 + cc];
            #pragma unroll
            for (int r = 0; r < 8; r++) {
                float sf = sc[(i0 + r) * 129 + j];
                #pragma unroll
                for (int cc = 0; cc < 4; cc++) acc[r][cc] += sf * xv[cc];
            }
        }
        #pragma unroll
        for (int r = 0; r < 8; r++) {
            size_t ybase = (size_t)(m0 + i0 + r) * DINNER + h * HD + p0;
            #pragma unroll
            for (int cc = 0; cc < 4; cc++) y[ybase + cc] = acc[r][cc];
        }
    }
    {
        int n = tid >> 2;
        int p0 = (tid & 3) * 16;
        float acc[16];
        #pragma unroll
        for (int cc = 0; cc < 16; cc++) acc[cc] = 0.f;
        for (int j = 0; j < CHUNK; j++) {
            float w = dend[j] * Bs[j * 65 + n];
            #pragma unroll
            for (int cc = 0; cc < 16; cc++) acc[cc] += w * xs[j * 65 + p0 + cc];
        }
        size_t off = ((size_t)((b * NCHUNK + c) * NH + h)) * (DSTATE * HD) + n * HD + p0;
        #pragma unroll
        for (int cc = 0; cc < 16; cc++) Sg[off + cc] = acc[cc];
        if (tid == 0) Ag[(b * NCHUNK + c) * NH + h] = expf(cum[CHUNK - 1]);
    }
    if (tid < CHUNK)
        cumg[((size_t)((b * NCHUNK + c) * NH + h)) * CHUNK + tid] = cum[tid];
}

// ------------------------------ inter-chunk state recurrence ----------------
__global__ void state_scan_kernel(const float* __restrict__ Sg, const float* __restrict__ Ag,
                                  float* __restrict__ Hp) {
    int b = blockIdx.x / NH, h = blockIdx.x % NH;
    int tid = threadIdx.x;
    float H[16];
    #pragma unroll
    for (int k = 0; k < 16; k++) H[k] = 0.f;
    for (int c = 0; c < NCHUNK; c++) {
        size_t off = ((size_t)((b * NCHUNK + c) * NH + h)) * (DSTATE * HD);
        float Ac = Ag[(b * NCHUNK + c) * NH + h];
        #pragma unroll
        for (int k = 0; k < 16; k++) {
            int e = tid + k * 256;
            Hp[off + e] = H[k];
            H[k] = Ac * H[k] + Sg[off + e];
        }
    }
}

// ------------------------------ y_inter + D*x + gating ---------------------
__global__ void y_inter_kernel(const float* __restrict__ zx, const float* __restrict__ xBC,
                               const float* __restrict__ Hp, const float* __restrict__ cumg,
                               const float* __restrict__ Dvec, const float* __restrict__ zb,
                               float* __restrict__ y) {
    extern __shared__ float sm[];
    float* Cs  = sm;                  // 128*65
    float* xs  = Cs + CHUNK * 65;     // 128*65
    float* Hs  = xs + CHUNK * 65;     // 64*65
    float* cum = Hs + DSTATE * 65;    // 128

    int h = blockIdx.x % NH;
    int c = (blockIdx.x / NH) % NCHUNK;
    int b = blockIdx.x / (NH * NCHUNK);
    int tid = threadIdx.x;
    int m0 = b * LSEQ + c * CHUNK;
    size_t hoff = (size_t)((b * NCHUNK + c) * NH + h);

    for (int idx = tid; idx < CHUNK * HD; idx += 256) {
        int i = idx >> 6, p = idx & 63;
        size_t rowb = (size_t)(m0 + i) * CONVD;
        xs[i * 65 + p] = xBC[rowb + h * HD + p];
        Cs[i * 65 + p] = xBC[rowb + DINNER + NH * DSTATE + h * DSTATE + p];
    }
    for (int idx = tid; idx < DSTATE * HD; idx += 256)
        Hs[(idx >> 6) * 65 + (idx & 63)] = Hp[hoff * (DSTATE * HD) + idx];
    if (tid < CHUNK) cum[tid] = cumg[hoff * CHUNK + tid];
    __syncthreads();

    int i = tid >> 1;
    int p0 = (tid & 1) * 32;
    float acc[32];
    #pragma unroll
    for (int cc = 0; cc < 32; cc++) acc[cc] = 0.f;
    for (int n = 0; n < DSTATE; n++) {
        float cv = Cs[i * 65 + n];
        #pragma unroll
        for (int cc = 0; cc < 32; cc++) acc[cc] += cv * Hs[n * 65 + p0 + cc];
    }
    float e = expf(cum[i]);
    float Dh = Dvec[h];
    int m = m0 + i;
    size_t ybase = (size_t)m * DINNER + h * HD;
    size_t zbase = (size_t)m * DINPROJ + h * HD;
    #pragma unroll
    for (int cc = 0; cc < 32; cc++) {
        int p = p0 + cc;
        float yt = y[ybase + p] + e * acc[cc] + Dh * xs[i * 65 + p];
        float g = zx[zbase + p] + zb[h * HD + p];
        float sg = g / (1.f + expf(-g));
        y[ybase + p] = tf32r(yt * sg);   // rounded: feeds out_proj tf32 GEMM
    }
}

// ------------------------------ MLP elementwise -----------------------------
__global__ void silu_mul_kernel(float* __restrict__ gate, const float* __restrict__ up,
                                size_t n) {
    size_t i = (size_t)blockIdx.x * blockDim.x + threadIdx.x;
    if (i < n) {
        float g = gate[i];
        gate[i] = tf32r((g / (1.f + expf(-g))) * up[i]);  // feeds down tf32 GEMM
    }
}

// ------------------------------ launch --------------------------------------
extern "C" void kernel_launch(void* const* d_in, const int* in_sizes, int n_in,
                              void* d_out, int out_size) {
    const float* hidden     = (const float*)d_in[0];
    const float* in_proj_w  = (const float*)d_in[1];
    const float* z_bias     = (const float*)d_in[2];
    const float* conv_w     = (const float*)d_in[3];
    const float* conv_b     = (const float*)d_in[4];
    const float* Dvec       = (const float*)d_in[5];
    const float* out_proj_w = (const float*)d_in[6];
    const float* norm1_w    = (const float*)d_in[7];
    const float* norm2_w    = (const float*)d_in[8];
    const float* gate_w     = (const float*)d_in[9];
    const float* up_w       = (const float*)d_in[10];
    const float* down_w     = (const float*)d_in[11];
    float* out = (float*)d_out;

    float *h1, *zx, *xbc, *y, *S, *A, *cumg, *Hp, *h2, *h3, *gate, *up;
    float *wip, *wop, *wg, *wu, *wd;
    cudaGetSymbolAddress((void**)&h1,   g_h1);
    cudaGetSymbolAddress((void**)&zx,   g_zx);
    cudaGetSymbolAddress((void**)&xbc,  g_xBC);
    cudaGetSymbolAddress((void**)&y,    g_y);
    cudaGetSymbolAddress((void**)&S,    g_S);
    cudaGetSymbolAddress((void**)&A,    g_Ac);
    cudaGetSymbolAddress((void**)&cumg, g_cum);
    cudaGetSymbolAddress((void**)&Hp,   g_Hp);
    cudaGetSymbolAddress((void**)&h2,   g_h2);
    cudaGetSymbolAddress((void**)&h3,   g_h3);
    cudaGetSymbolAddress((void**)&gate, g_gate);
    cudaGetSymbolAddress((void**)&up,   g_up);
    cudaGetSymbolAddress((void**)&wip,  g_wip);
    cudaGetSymbolAddress((void**)&wop,  g_wop);
    cudaGetSymbolAddress((void**)&wg,   g_wg);
    cudaGetSymbolAddress((void**)&wu,   g_wu);
    cudaGetSymbolAddress((void**)&wd,   g_wd);

    const int SMEM_INTRA  = (3 * CHUNK * 65 + CHUNK * 129 + 2 * CHUNK) * sizeof(float);
    const int SMEM_YINTER = (2 * CHUNK * 65 + DSTATE * 65 + CHUNK) * sizeof(float);
    const int SMEM_GEMM   = 4 * 128 * BKP * sizeof(float);   // 2 bufs x (A+W)
    cudaFuncSetAttribute(ssd_intra_kernel, cudaFuncAttributeMaxDynamicSharedMemorySize, SMEM_INTRA);
    cudaFuncSetAttribute(y_inter_kernel,  cudaFuncAttributeMaxDynamicSharedMemorySize, SMEM_YINTER);
    cudaFuncSetAttribute(tf32_gemm_kernel, cudaFuncAttributeMaxDynamicSharedMemorySize, SMEM_GEMM);

    // 0) pre-round weights to tf32 (cheap elementwise pre-pass)
    {
        auto rr = [&](const float* src, float* dst, size_t n) {
            int n4 = (int)(n / 4);
            round_tf32_kernel<<<(n4 + 255) / 256, 256>>>(src, dst, n4);
        };
        rr(in_proj_w,  wip, (size_t)DINPROJ * DMODEL);
        rr(out_proj_w, wop, (size_t)DMODEL * DINNER);
        rr(gate_w,     wg,  (size_t)DFF * DMODEL);
        rr(up_w,       wu,  (size_t)DFF * DMODEL);
        rr(down_w,     wd,  (size_t)DMODEL * DFF);
    }

    // 1) rmsnorm 1 (tf32-rounded output)
    rmsnorm_kernel<<<MTOK, 256>>>(hidden, norm1_w, h1);
    // 2) in_proj: zx = h1 @ in_proj_w^T   [4096 x 8224]
    tf32_gemm_kernel<<<dim3((DINPROJ + 127) / 128, MTOK / 128), 256, SMEM_GEMM>>>(
        h1, wip, nullptr, zx, MTOK, DINPROJ, DMODEL);
    // 3) causal depthwise conv over xBC slice
    conv1d_kernel<<<(int)(((size_t)MTOK * CONVD + 255) / 256), 256>>>(zx, conv_w, conv_b, xbc);
    // 4) SSD intra-chunk (y_intra, S, A, cum)
    ssd_intra_kernel<<<BATCH * NCHUNK * NH, 256, SMEM_INTRA>>>(zx, xbc, y, S, A, cumg);
    // 5) inter-chunk state recurrence
    state_scan_kernel<<<BATCH * NH, 256>>>(S, A, Hp);
    // 6) y_inter + D*x + silu(z) gating (in-place on y, tf32-rounded)
    y_inter_kernel<<<BATCH * NCHUNK * NH, 256, SMEM_YINTER>>>(zx, xbc, Hp, cumg, Dvec, z_bias, y);
    // 7) out_proj + residual: h2 = y @ out_proj_w^T + hidden
    tf32_gemm_kernel<<<dim3(DMODEL / 128, MTOK / 128), 256, SMEM_GEMM>>>(
        y, wop, hidden, h2, MTOK, DMODEL, DINNER);
    // 8) rmsnorm 2 (tf32-rounded output)
    rmsnorm_kernel<<<MTOK, 256>>>(h2, norm2_w, h3);
    // 9) MLP gate / up
    tf32_gemm_kernel<<<dim3(DFF / 128, MTOK / 128), 256, SMEM_GEMM>>>(
        h3, wg, nullptr, gate, MTOK, DFF, DMODEL);
    tf32_gemm_kernel<<<dim3(DFF / 128, MTOK / 128), 256, SMEM_GEMM>>>(
        h3, wu, nullptr, up, MTOK, DFF, DMODEL);
    // 10) act = silu(gate) * up (in-place on gate, tf32-rounded)
    silu_mul_kernel<<<(int)(((size_t)MTOK * DFF + 255) / 256), 256>>>(
        gate, up, (size_t)MTOK * DFF);
    // 11) down + residual: out = act @ down_w^T + h2
    tf32_gemm_kernel<<<dim3(DMODEL / 128, MTOK / 128), 256, SMEM_GEMM>>>(
        gate, wd, h2, out, MTOK, DMODEL, DFF);
}

// round 12
// speedup vs baseline: 4.2046x; 1.1348x over previous
#include <cuda_runtime.h>
#include <math.h>
#include <stdint.h>

#define BATCH   2
#define LSEQ    2048
#define MTOK    (BATCH*LSEQ)          // 4096
#define DMODEL  2048
#define DINNER  2048
#define NH      32
#define DSTATE  64
#define HD      64
#define CHUNK   128
#define NCHUNK  (LSEQ/CHUNK)          // 16
#define DFF     8192
#define CONVD   (DINNER + 2*NH*DSTATE)          // 6144
#define DINPROJ (2*DINNER + 2*NH*DSTATE + NH)   // 8224
#define DTOFF   (DINNER + CONVD)                // 8192

// ------------------------- scratch (device globals, no allocs) -------------
__device__ float g_h1  [(size_t)MTOK*DMODEL];
__device__ float g_zx  [(size_t)MTOK*DINPROJ];
__device__ float g_xBC [(size_t)MTOK*CONVD];
__device__ float g_y   [(size_t)MTOK*DINNER];
__device__ float g_S   [(size_t)BATCH*NCHUNK*NH*DSTATE*HD];
__device__ float g_Ac  [(size_t)BATCH*NCHUNK*NH];
__device__ float g_cum [(size_t)BATCH*NCHUNK*NH*CHUNK];
__device__ float g_Hp  [(size_t)BATCH*NCHUNK*NH*DSTATE*HD];
__device__ float g_h2  [(size_t)MTOK*DMODEL];
__device__ float g_h3  [(size_t)MTOK*DMODEL];
__device__ float g_gate[(size_t)MTOK*DFF];
__device__ float g_up  [(size_t)MTOK*DFF];
// tf32-rounded weight copies
__device__ float g_wip [(size_t)DINPROJ*DMODEL];
__device__ float g_wop [(size_t)DMODEL*DINNER];
__device__ float g_wg  [(size_t)DFF*DMODEL];
__device__ float g_wu  [(size_t)DFF*DMODEL];
__device__ float g_wd  [(size_t)DMODEL*DFF];

// ------------------------------ helpers ------------------------------------
__device__ __forceinline__ float tf32r(float x) {
    uint32_t u;
    asm("cvt.rna.tf32.f32 %0, %1;" : "=r"(u) : "f"(x));
    return __uint_as_float(u);
}
__device__ __forceinline__ uint32_t smem_u32(const void* p) {
    uint32_t r;
    asm("{ .reg .u64 t; cvta.to.shared.u64 t, %1; cvt.u32.u64 %0, t; }" : "=r"(r) : "l"(p));
    return r;
}
__device__ __forceinline__ void cpa16(uint32_t dst, const void* src, int bytes) {
    asm volatile("cp.async.cg.shared.global [%0], [%1], 16, %2;\n"
                 :: "r"(dst), "l"(src), "r"(bytes));
}
__device__ __forceinline__ void cpa_commit() { asm volatile("cp.async.commit_group;\n"); }
__device__ __forceinline__ void cpa_wait0()  { asm volatile("cp.async.wait_group 0;\n"); }
__device__ __forceinline__ void cpa_wait1()  { asm volatile("cp.async.wait_group 1;\n"); }

// round fp32 buffer to tf32 (float4 granularity; all sizes divisible by 4)
__global__ void round_tf32_kernel(const float* __restrict__ in, float* __restrict__ out,
                                  int n4) {
    int i = blockIdx.x * blockDim.x + threadIdx.x;
    if (i < n4) {
        float4 v = ((const float4*)in)[i];
        v.x = tf32r(v.x); v.y = tf32r(v.y); v.z = tf32r(v.z); v.w = tf32r(v.w);
        ((float4*)out)[i] = v;
    }
}

// ------------------------------ rmsnorm (tf32-rounded output) ---------------
__global__ void rmsnorm_kernel(const float* __restrict__ x, const float* __restrict__ w,
                               float* __restrict__ y) {
    int row = blockIdx.x;
    const float* xr = x + (size_t)row * DMODEL;
    float ss = 0.f;
    for (int c = threadIdx.x; c < DMODEL; c += 256) { float v = xr[c]; ss += v * v; }
    #pragma unroll
    for (int off = 16; off; off >>= 1) ss += __shfl_xor_sync(0xffffffffu, ss, off);
    __shared__ float red[8];
    if ((threadIdx.x & 31) == 0) red[threadIdx.x >> 5] = ss;
    __syncthreads();
    if (threadIdx.x < 8) {
        float v = red[threadIdx.x];
        #pragma unroll
        for (int off = 4; off; off >>= 1) v += __shfl_xor_sync(0xffu, v, off);
        if (threadIdx.x == 0) red[0] = v;
    }
    __syncthreads();
    float inv = rsqrtf(red[0] / (float)DMODEL + 1e-5f);
    float* yr = y + (size_t)row * DMODEL;
    for (int c = threadIdx.x; c < DMODEL; c += 256) yr[c] = tf32r(w[c] * xr[c] * inv);
}

// ------------------------------ TF32 tensor-core GEMM -----------------------
// C = A * W^T (+ res). A:[M,K], W:[N,K] row-major, both pre-rounded to tf32.
// CTA tile 128x256, BK=32, 8 warps of 64x64, mma.sync.m16n8k8.tf32,
// 3-stage cp.async pipeline. 1 CTA/SM (162KB smem).
#define BKP 36   // smem row stride (floats) -> conflict-free fragment LDS
#define ASTG (128 * BKP)     // floats per A stage
#define BSTG (256 * BKP)     // floats per B stage

__global__ __launch_bounds__(256, 1) void tf32_gemm_kernel(
        const float* __restrict__ A, const float* __restrict__ W,
        const float* __restrict__ res, float* __restrict__ C,
        int M, int N, int K) {
    extern __shared__ float sm[];
    float* As = sm;                 // 3 * ASTG
    float* Ws = sm + 3 * ASTG;      // 3 * BSTG
    const uint32_t as_u = smem_u32(As);
    const uint32_t ws_u = smem_u32(Ws);

    int tid = threadIdx.x;
    int bm = blockIdx.y * 128, bn = blockIdx.x * 256;
    int lane = tid & 31, warp = tid >> 5;
    int wm = (warp >> 2) * 64;       // warp row offset (0 or 64)
    int wn = (warp & 3) * 64;        // warp col offset (0..192)
    int grp = lane >> 2, tig = lane & 3;

    float c[4][8][4];
    #pragma unroll
    for (int mt = 0; mt < 4; mt++)
        #pragma unroll
        for (int nt = 0; nt < 8; nt++)
            #pragma unroll
            for (int e = 0; e < 4; e++) c[mt][nt][e] = 0.f;

    const int ldrow = tid >> 3;        // 0..31
    const int ldc4  = (tid & 7) * 4;   // 0,4,..,28

    auto load_tile = [&](int t, int which) {
        int kb = t * 32;
        uint32_t ab = as_u + (uint32_t)which * ASTG * 4;
        uint32_t wb = ws_u + (uint32_t)which * BSTG * 4;
        #pragma unroll
        for (int i = 0; i < 4; i++) {          // A: 128 rows
            int row = ldrow + i * 32;
            cpa16(ab + (row * BKP + ldc4) * 4,
                  A + (size_t)(bm + row) * K + kb + ldc4, 16);
        }
        #pragma unroll
        for (int i = 0; i < 8; i++) {          // B: 256 rows
            int row = ldrow + i * 32;
            int n = bn + row;
            int nn = n < N ? n : (N - 1);
            cpa16(wb + (row * BKP + ldc4) * 4,
                  W + (size_t)nn * K + kb + ldc4, n < N ? 16 : 0);
        }
    };

    int ntiles = K / 32;
    load_tile(0, 0); cpa_commit();
    load_tile(1, 1); cpa_commit();

    for (int t = 0; t < ntiles; t++) {
        int buf = t % 3;
        if (t + 1 < ntiles) cpa_wait1(); else cpa_wait0();
        __syncthreads();
        if (t + 2 < ntiles) { load_tile(t + 2, (t + 2) % 3); cpa_commit(); }
        const float* Ab = As + buf * ASTG;
        const float* Wb = Ws + buf * BSTG;
        #pragma unroll
        for (int ks = 0; ks < 4; ks++) {
            int k = ks * 8;
            uint32_t af[4][4], bf[8][2];
            #pragma unroll
            for (int mt = 0; mt < 4; mt++) {
                const float* p = Ab + (wm + mt * 16 + grp) * BKP + k + tig;
                af[mt][0] = __float_as_uint(p[0]);
                af[mt][1] = __float_as_uint(p[8 * BKP]);
                af[mt][2] = __float_as_uint(p[4]);
                af[mt][3] = __float_as_uint(p[8 * BKP + 4]);
            }
            #pragma unroll
            for (int nt = 0; nt < 8; nt++) {
                const float* p = Wb + (wn + nt * 8 + grp) * BKP + k + tig;
                bf[nt][0] = __float_as_uint(p[0]);
                bf[nt][1] = __float_as_uint(p[4]);
            }
            #pragma unroll
            for (int mt = 0; mt < 4; mt++)
                #pragma unroll
                for (int nt = 0; nt < 8; nt++) {
                    asm volatile(
                        "mma.sync.aligned.m16n8k8.row.col.f32.tf32.tf32.f32 "
                        "{%0,%1,%2,%3}, {%4,%5,%6,%7}, {%8,%9}, {%0,%1,%2,%3};\n"
                        : "+f"(c[mt][nt][0]), "+f"(c[mt][nt][1]),
                          "+f"(c[mt][nt][2]), "+f"(c[mt][nt][3])
                        : "r"(af[mt][0]), "r"(af[mt][1]), "r"(af[mt][2]), "r"(af[mt][3]),
                          "r"(bf[nt][0]), "r"(bf[nt][1]));
                }
        }
        __syncthreads();
    }

    // epilogue
    #pragma unroll
    for (int mt = 0; mt < 4; mt++) {
        int r0 = bm + wm + mt * 16 + grp;
        #pragma unroll
        for (int nt = 0; nt < 8; nt++) {
            int col = bn + wn + nt * 8 + 2 * tig;
            if (col < N) {
                float v0 = c[mt][nt][0], v1 = c[mt][nt][1];
                float v2 = c[mt][nt][2], v3 = c[mt][nt][3];
                size_t o0 = (size_t)r0 * N + col;
                size_t o1 = (size_t)(r0 + 8) * N + col;
                if (res) {
                    v0 += res[o0]; v1 += res[o0 + 1];
                    v2 += res[o1]; v3 += res[o1 + 1];
                }
                *(float2*)(C + o0) = make_float2(v0, v1);
                *(float2*)(C + o1) = make_float2(v2, v3);
            }
        }
    }
}

// ------------------------------ causal depthwise conv ----------------------
__global__ void conv1d_kernel(const float* __restrict__ zx, const float* __restrict__ cw,
                              const float* __restrict__ cb, float* __restrict__ xBC) {
    size_t idx = (size_t)blockIdx.x * blockDim.x + threadIdx.x;
    if (idx >= (size_t)MTOK * CONVD) return;
    int c = (int)(idx % CONVD);
    int m = (int)(idx / CONVD);
    int t = m & (LSEQ - 1);
    float acc = cb[c];
    #pragma unroll
    for (int j = 0; j < 4; j++) {
        int tt = t - 3 + j;
        if (tt >= 0)
            acc += cw[c * 4 + j] * zx[(size_t)(m - 3 + j) * DINPROJ + DINNER + c];
    }
    xBC[idx] = acc;
}

// ------------------------------ SSD intra-chunk ----------------------------
__global__ void ssd_intra_kernel(const float* __restrict__ zx, const float* __restrict__ xBC,
                                 float* __restrict__ y, float* __restrict__ Sg,
                                 float* __restrict__ Ag, float* __restrict__ cumg) {
    extern __shared__ float sm[];
    float* xs   = sm;                       // 128*65
    float* Bs   = xs + CHUNK * 65;          // 128*65
    float* Cs   = Bs + CHUNK * 65;          // 128*65
    float* sc   = Cs + CHUNK * 65;          // 128*129
    float* cum  = sc + CHUNK * 129;         // 128
    float* dend = cum + CHUNK;              // 128

    int h = blockIdx.x % NH;
    int c = (blockIdx.x / NH) % NCHUNK;
    int b = blockIdx.x / (NH * NCHUNK);
    int tid = threadIdx.x;
    int m0 = b * LSEQ + c * CHUNK;

    for (int idx = tid; idx < CHUNK * HD; idx += 256) {
        int i = idx >> 6, p = idx & 63;
        size_t rowb = (size_t)(m0 + i) * CONVD;
        xs[i * 65 + p] = xBC[rowb + h * HD + p];
        Bs[i * 65 + p] = xBC[rowb + DINNER + h * DSTATE + p];
        Cs[i * 65 + p] = xBC[rowb + DINNER + NH * DSTATE + h * DSTATE + p];
    }
    if (tid < CHUNK) {
        float d = zx[(size_t)(m0 + tid) * DINPROJ + DTOFF + h];
        float sp = (d > 20.f) ? d : log1pf(expf(d));
        cum[tid] = -sp;
    }
    __syncthreads();
    for (int off = 1; off < CHUNK; off <<= 1) {
        float v = 0.f;
        if (tid < CHUNK && tid >= off) v = cum[tid - off];
        __syncthreads();
        if (tid < CHUNK && tid >= off) cum[tid] += v;
        __syncthreads();
    }
    if (tid < CHUNK) dend[tid] = expf(cum[CHUNK - 1] - cum[tid]);
    __syncthreads();

    int ty = tid >> 4, tx = tid & 15;
    {
        float acc[8][8];
        #pragma unroll
        for (int r = 0; r < 8; r++)
            #pragma unroll
            for (int s = 0; s < 8; s++) acc[r][s] = 0.f;
        int i0 = ty * 8;
        for (int n = 0; n < DSTATE; n++) {
            float cf[8], bf[8];
            #pragma unroll
            for (int r = 0; r < 8; r++) cf[r] = Cs[(i0 + r) * 65 + n];
            #pragma unroll
            for (int s = 0; s < 8; s++) bf[s] = Bs[(tx + 16 * s) * 65 + n];
            #pragma unroll
            for (int r = 0; r < 8; r++)
                #pragma unroll
                for (int s = 0; s < 8; s++) acc[r][s] += cf[r] * bf[s];
        }
        #pragma unroll
        for (int r = 0; r < 8; r++) {
            int i = i0 + r;
            float ci = cum[i];
            #pragma unroll
            for (int s = 0; s < 8; s++) {
                int j = tx + 16 * s;
                sc[i * 129 + j] = (j <= i) ? expf(ci - cum[j]) * acc[r][s] : 0.f;
            }
        }
    }
    __syncthreads();
    {
        float acc[8][4];
        #pragma unroll
        for (int r = 0; r < 8; r++)
            #pragma unroll
            for (int cc = 0; cc < 4; cc++) acc[r][cc] = 0.f;
        int i0 = ty * 8, p0 = tx * 4;
        for (int j = 0; j < CHUNK; j++) {
            float xv[4];
            #pragma unroll
            for (int cc = 0; cc < 4; cc++) xv[cc] = xs[j * 65 + p0 + cc];
            #pragma unroll
            for (int r = 0; r < 8; r++) {
                float sf = sc[(i0 + r) * 129 + j];
                #pragma unroll
                for (int cc = 0; cc < 4; cc++) acc[r][cc] += sf * xv[cc];
            }
        }
        #pragma unroll
        for (int r = 0; r < 8; r++) {
            size_t ybase = (size_t)(m0 + i0 + r) * DINNER + h * HD + p0;
            #pragma unroll
            for (int cc = 0; cc < 4; cc++) y[ybase + cc] = acc[r][cc];
        }
    }
    {
        int n = tid >> 2;
        int p0 = (tid & 3) * 16;
        float acc[16];
        #pragma unroll
        for (int cc = 0; cc < 16; cc++) acc[cc] = 0.f;
        for (int j = 0; j < CHUNK; j++) {
            float w = dend[j] * Bs[j * 65 + n];
            #pragma unroll
            for (int cc = 0; cc < 16; cc++) acc[cc] += w * xs[j * 65 + p0 + cc];
        }
        size_t off = ((size_t)((b * NCHUNK + c) * NH + h)) * (DSTATE * HD) + n * HD + p0;
        #pragma unroll
        for (int cc = 0; cc < 16; cc++) Sg[off + cc] = acc[cc];
        if (tid == 0) Ag[(b * NCHUNK + c) * NH + h] = expf(cum[CHUNK - 1]);
    }
    if (tid < CHUNK)
        cumg[((size_t)((b * NCHUNK + c) * NH + h)) * CHUNK + tid] = cum[tid];
}

// ------------------------------ inter-chunk state recurrence ----------------
__global__ void state_scan_kernel(const float* __restrict__ Sg, const float* __restrict__ Ag,
                                  float* __restrict__ Hp) {
    int b = blockIdx.x / NH, h = blockIdx.x % NH;
    int tid = threadIdx.x;
    float H[16];
    #pragma unroll
    for (int k = 0; k < 16; k++) H[k] = 0.f;
    for (int c = 0; c < NCHUNK; c++) {
        size_t off = ((size_t)((b * NCHUNK + c) * NH + h)) * (DSTATE * HD);
        float Ac = Ag[(b * NCHUNK + c) * NH + h];
        #pragma unroll
        for (int k = 0; k < 16; k++) {
            int e = tid + k * 256;
            Hp[off + e] = H[k];
            H[k] = Ac * H[k] + Sg[off + e];
        }
    }
}

// ------------------------------ y_inter + D*x + gating ---------------------
__global__ void y_inter_kernel(const float* __restrict__ zx, const float* __restrict__ xBC,
                               const float* __restrict__ Hp, const float* __restrict__ cumg,
                               const float* __restrict__ Dvec, const float* __restrict__ zb,
                               float* __restrict__ y) {
    extern __shared__ float sm[];
    float* Cs  = sm;                  // 128*65
    float* xs  = Cs + CHUNK * 65;     // 128*65
    float* Hs  = xs + CHUNK * 65;     // 64*65
    float* cum = Hs + DSTATE * 65;    // 128

    int h = blockIdx.x % NH;
    int c = (blockIdx.x / NH) % NCHUNK;
    int b = blockIdx.x / (NH * NCHUNK);
    int tid = threadIdx.x;
    int m0 = b * LSEQ + c * CHUNK;
    size_t hoff = (size_t)((b * NCHUNK + c) * NH + h);

    for (int idx = tid; idx < CHUNK * HD; idx += 256) {
        int i = idx >> 6, p = idx & 63;
        size_t rowb = (size_t)(m0 + i) * CONVD;
        xs[i * 65 + p] = xBC[rowb + h * HD + p];
        Cs[i * 65 + p] = xBC[rowb + DINNER + NH * DSTATE + h * DSTATE + p];
    }
    for (int idx = tid; idx < DSTATE * HD; idx += 256)
        Hs[(idx >> 6) * 65 + (idx & 63)] = Hp[hoff * (DSTATE * HD) + idx];
    if (tid < CHUNK) cum[tid] = cumg[hoff * CHUNK + tid];
    __syncthreads();

    int i = tid >> 1;
    int p0 = (tid & 1) * 32;
    float acc[32];
    #pragma unroll
    for (int cc = 0; cc < 32; cc++) acc[cc] = 0.f;
    for (int n = 0; n < DSTATE; n++) {
        float cv = Cs[i * 65 + n];
        #pragma unroll
        for (int cc = 0; cc < 32; cc++) acc[cc] += cv * Hs[n * 65 + p0 + cc];
    }
    float e = expf(cum[i]);
    float Dh = Dvec[h];
    int m = m0 + i;
    size_t ybase = (size_t)m * DINNER + h * HD;
    size_t zbase = (size_t)m * DINPROJ + h * HD;
    #pragma unroll
    for (int cc = 0; cc < 32; cc++) {
        int p = p0 + cc;
        float yt = y[ybase + p] + e * acc[cc] + Dh * xs[i * 65 + p];
        float g = zx[zbase + p] + zb[h * HD + p];
        float sg = g / (1.f + expf(-g));
        y[ybase + p] = tf32r(yt * sg);
    }
}

// ------------------------------ MLP elementwise -----------------------------
__global__ void silu_mul_kernel(float* __restrict__ gate, const float* __restrict__ up,
                                size_t n) {
    size_t i = (size_t)blockIdx.x * blockDim.x + threadIdx.x;
    if (i < n) {
        float g = gate[i];
        gate[i] = tf32r((g / (1.f + expf(-g))) * up[i]);
    }
}

// ------------------------------ launch --------------------------------------
extern "C" void kernel_launch(void* const* d_in, const int* in_sizes, int n_in,
                              void* d_out, int out_size) {
    const float* hidden     = (const float*)d_in[0];
    const float* in_proj_w  = (const float*)d_in[1];
    const float* z_bias     = (const float*)d_in[2];
    const float* conv_w     = (const float*)d_in[3];
    const float* conv_b     = (const float*)d_in[4];
    const float* Dvec       = (const float*)d_in[5];
    const float* out_proj_w = (const float*)d_in[6];
    const float* norm1_w    = (const float*)d_in[7];
    const float* norm2_w    = (const float*)d_in[8];
    const float* gate_w     = (const float*)d_in[9];
    const float* up_w       = (const float*)d_in[10];
    const float* down_w     = (const float*)d_in[11];
    float* out = (float*)d_out;

    float *h1, *zx, *xbc, *y, *S, *A, *cumg, *Hp, *h2, *h3, *gate, *up;
    float *wip, *wop, *wg, *wu, *wd;
    cudaGetSymbolAddress((void**)&h1,   g_h1);
    cudaGetSymbolAddress((void**)&zx,   g_zx);
    cudaGetSymbolAddress((void**)&xbc,  g_xBC);
    cudaGetSymbolAddress((void**)&y,    g_y);
    cudaGetSymbolAddress((void**)&S,    g_S);
    cudaGetSymbolAddress((void**)&A,    g_Ac);
    cudaGetSymbolAddress((void**)&cumg, g_cum);
    cudaGetSymbolAddress((void**)&Hp,   g_Hp);
    cudaGetSymbolAddress((void**)&h2,   g_h2);
    cudaGetSymbolAddress((void**)&h3,   g_h3);
    cudaGetSymbolAddress((void**)&gate, g_gate);
    cudaGetSymbolAddress((void**)&up,   g_up);
    cudaGetSymbolAddress((void**)&wip,  g_wip);
    cudaGetSymbolAddress((void**)&wop,  g_wop);
    cudaGetSymbolAddress((void**)&wg,   g_wg);
    cudaGetSymbolAddress((void**)&wu,   g_wu);
    cudaGetSymbolAddress((void**)&wd,   g_wd);

    const int SMEM_INTRA  = (3 * CHUNK * 65 + CHUNK * 129 + 2 * CHUNK) * sizeof(float);
    const int SMEM_YINTER = (2 * CHUNK * 65 + DSTATE * 65 + CHUNK) * sizeof(float);
    const int SMEM_GEMM   = 3 * (ASTG + BSTG) * sizeof(float);   // 3 stages
    cudaFuncSetAttribute(ssd_intra_kernel, cudaFuncAttributeMaxDynamicSharedMemorySize, SMEM_INTRA);
    cudaFuncSetAttribute(y_inter_kernel,  cudaFuncAttributeMaxDynamicSharedMemorySize, SMEM_YINTER);
    cudaFuncSetAttribute(tf32_gemm_kernel, cudaFuncAttributeMaxDynamicSharedMemorySize, SMEM_GEMM);

    // 0) pre-round weights to tf32
    {
        auto rr = [&](const float* src, float* dst, size_t n) {
            int n4 = (int)(n / 4);
            round_tf32_kernel<<<(n4 + 255) / 256, 256>>>(src, dst, n4);
        };
        rr(in_proj_w,  wip, (size_t)DINPROJ * DMODEL);
        rr(out_proj_w, wop, (size_t)DMODEL * DINNER);
        rr(gate_w,     wg,  (size_t)DFF * DMODEL);
        rr(up_w,       wu,  (size_t)DFF * DMODEL);
        rr(down_w,     wd,  (size_t)DMODEL * DFF);
    }

    // 1) rmsnorm 1
    rmsnorm_kernel<<<MTOK, 256>>>(hidden, norm1_w, h1);
    // 2) in_proj: zx = h1 @ in_proj_w^T   [4096 x 8224]
    tf32_gemm_kernel<<<dim3((DINPROJ + 255) / 256, MTOK / 128), 256, SMEM_GEMM>>>(
        h1, wip, nullptr, zx, MTOK, DINPROJ, DMODEL);
    // 3) causal depthwise conv
    conv1d_kernel<<<(int)(((size_t)MTOK * CONVD + 255) / 256), 256>>>(zx, conv_w, conv_b, xbc);
    // 4) SSD intra-chunk
    ssd_intra_kernel<<<BATCH * NCHUNK * NH, 256, SMEM_INTRA>>>(zx, xbc, y, S, A, cumg);
    // 5) inter-chunk state recurrence
    state_scan_kernel<<<BATCH * NH, 256>>>(S, A, Hp);
    // 6) y_inter + D*x + gating
    y_inter_kernel<<<BATCH * NCHUNK * NH, 256, SMEM_YINTER>>>(zx, xbc, Hp, cumg, Dvec, z_bias, y);
    // 7) out_proj + residual
    tf32_gemm_kernel<<<dim3(DMODEL / 256, MTOK / 128), 256, SMEM_GEMM>>>(
        y, wop, hidden, h2, MTOK, DMODEL, DINNER);
    // 8) rmsnorm 2
    rmsnorm_kernel<<<MTOK, 256>>>(h2, norm2_w, h3);
    // 9) MLP gate / up
    tf32_gemm_kernel<<<dim3(DFF / 256, MTOK / 128), 256, SMEM_GEMM>>>(
        h3, wg, nullptr, gate, MTOK, DFF, DMODEL);
    tf32_gemm_kernel<<<dim3(DFF / 256, MTOK / 128), 256, SMEM_GEMM>>>(
        h3, wu, nullptr, up, MTOK, DFF, DMODEL);
    // 10) act = silu(gate) * up
    silu_mul_kernel<<<(int)(((size_t)MTOK * DFF + 255) / 256), 256>>>(
        gate, up, (size_t)MTOK * DFF);
    // 11) down + residual
    tf32_gemm_kernel<<<dim3(DMODEL / 256, MTOK / 128), 256, SMEM_GEMM>>>(
        gate, wd, h2, out, MTOK, DMODEL, DFF);
}

// round 13
// speedup vs baseline: 7.4153x; 1.7636x over previous
#include <cuda_runtime.h>
#include <cuda_fp16.h>
#include <math.h>
#include <stdint.h>

#define BATCH   2
#define LSEQ    2048
#define MTOK    (BATCH*LSEQ)          // 4096
#define DMODEL  2048
#define DINNER  2048
#define NH      32
#define DSTATE  64
#define HD      64
#define CHUNK   128
#define NCHUNK  (LSEQ/CHUNK)          // 16
#define DFF     8192
#define CONVD   (DINNER + 2*NH*DSTATE)          // 6144
#define DINPROJ (2*DINNER + 2*NH*DSTATE + NH)   // 8224
#define DTOFF   (DINNER + CONVD)                // 8192

// ------------------------- scratch (device globals, no allocs) -------------
__device__ float g_zx  [(size_t)MTOK*DINPROJ];
__device__ float g_xBC [(size_t)MTOK*CONVD];
__device__ float g_y   [(size_t)MTOK*DINNER];
__device__ float g_S   [(size_t)BATCH*NCHUNK*NH*DSTATE*HD];
__device__ float g_Ac  [(size_t)BATCH*NCHUNK*NH];
__device__ float g_cum [(size_t)BATCH*NCHUNK*NH*CHUNK];
__device__ float g_Hp  [(size_t)BATCH*NCHUNK*NH*DSTATE*HD];
__device__ float g_h2  [(size_t)MTOK*DMODEL];
__device__ float g_gate[(size_t)MTOK*DFF];
__device__ float g_up  [(size_t)MTOK*DFF];
// fp16 GEMM activation inputs
__device__ __half g_h1h [(size_t)MTOK*DMODEL];
__device__ __half g_yh  [(size_t)MTOK*DINNER];
__device__ __half g_h3h [(size_t)MTOK*DMODEL];
__device__ __half g_acth[(size_t)MTOK*DFF];
// fp16 weight copies
__device__ __half g_wip [(size_t)DINPROJ*DMODEL];
__device__ __half g_wop [(size_t)DMODEL*DINNER];
__device__ __half g_wg  [(size_t)DFF*DMODEL];
__device__ __half g_wu  [(size_t)DFF*DMODEL];
__device__ __half g_wd  [(size_t)DMODEL*DFF];

// ------------------------------ helpers ------------------------------------
__device__ __forceinline__ uint32_t smem_u32(const void* p) {
    uint32_t r;
    asm("{ .reg .u64 t; cvta.to.shared.u64 t, %1; cvt.u32.u64 %0, t; }" : "=r"(r) : "l"(p));
    return r;
}
__device__ __forceinline__ void cpa16(uint32_t dst, const void* src, int bytes) {
    asm volatile("cp.async.cg.shared.global [%0], [%1], 16, %2;\n"
                 :: "r"(dst), "l"(src), "r"(bytes));
}
__device__ __forceinline__ void cpa_commit() { asm volatile("cp.async.commit_group;\n"); }
__device__ __forceinline__ void cpa_wait0()  { asm volatile("cp.async.wait_group 0;\n"); }
__device__ __forceinline__ void cpa_wait1()  { asm volatile("cp.async.wait_group 1;\n"); }

#define LDSM4(r0, r1, r2, r3, addr) \
    asm volatile("ldmatrix.sync.aligned.m8n8.x4.shared.b16 {%0,%1,%2,%3}, [%4];" \
        : "=r"(r0), "=r"(r1), "=r"(r2), "=r"(r3) : "r"(addr))

// fp32 -> fp16 weight conversion (float4 -> 4 halves)
__global__ void w2h_kernel(const float* __restrict__ in, __half* __restrict__ out, int n4) {
    int i = blockIdx.x * blockDim.x + threadIdx.x;
    if (i < n4) {
        float4 v = ((const float4*)in)[i];
        __half2 h0 = __floats2half2_rn(v.x, v.y);
        __half2 h1 = __floats2half2_rn(v.z, v.w);
        uint2 st;
        st.x = *(uint32_t*)&h0;
        st.y = *(uint32_t*)&h1;
        ((uint2*)out)[i] = st;
    }
}

// ------------------------------ rmsnorm (fp16 output) -----------------------
__global__ void rmsnorm_kernel(const float* __restrict__ x, const float* __restrict__ w,
                               __half* __restrict__ y) {
    int row = blockIdx.x;
    const float* xr = x + (size_t)row * DMODEL;
    float ss = 0.f;
    for (int c = threadIdx.x; c < DMODEL; c += 256) { float v = xr[c]; ss += v * v; }
    #pragma unroll
    for (int off = 16; off; off >>= 1) ss += __shfl_xor_sync(0xffffffffu, ss, off);
    __shared__ float red[8];
    if ((threadIdx.x & 31) == 0) red[threadIdx.x >> 5] = ss;
    __syncthreads();
    if (threadIdx.x < 8) {
        float v = red[threadIdx.x];
        #pragma unroll
        for (int off = 4; off; off >>= 1) v += __shfl_xor_sync(0xffu, v, off);
        if (threadIdx.x == 0) red[0] = v;
    }
    __syncthreads();
    float inv = rsqrtf(red[0] / (float)DMODEL + 1e-5f);
    __half* yr = y + (size_t)row * DMODEL;
    for (int c = threadIdx.x; c < DMODEL; c += 256)
        yr[c] = __float2half_rn(w[c] * xr[c] * inv);
}

// ------------------------------ FP16 tensor-core GEMM -----------------------
// C(fp32) = A(fp16) * W(fp16)^T (+ res fp32). A:[M,K], W:[N,K] row-major.
// CTA tile 128x256, BK=64, 8 warps of 64x64, mma.sync.m16n8k16.f16 (fp32 acc),
// ldmatrix fragment loads, 3-stage cp.async pipeline. 1 CTA/SM (~162KB smem).
#define HROW 144                 // bytes per smem row (64 halves + 8 pad)
#define ASTGB (128 * HROW)       // A stage bytes  (18432)
#define BSTGB (256 * HROW)       // B stage bytes  (36864)
#define STGB  (ASTGB + BSTGB)    // 55296
#define SMEM_HGEMM (3 * STGB)    // 165888

__global__ __launch_bounds__(256, 1) void hgemm_kernel(
        const __half* __restrict__ A, const __half* __restrict__ W,
        const float* __restrict__ res, float* __restrict__ C,
        int M, int N, int K) {
    extern __shared__ char smraw[];
    const uint32_t sb = smem_u32(smraw);

    int tid = threadIdx.x;
    int bm = blockIdx.y * 128, bn = blockIdx.x * 256;
    int lane = tid & 31, warp = tid >> 5;
    int wm = (warp >> 2) * 64;       // 0 or 64
    int wn = (warp & 3) * 64;        // 0..192
    int grp = lane >> 2, tig = lane & 3;

    // ldmatrix per-lane address components (mat = lane>>3, r = lane&7)
    int mat = lane >> 3, r = lane & 7;
    uint32_t a_off = (uint32_t)(((mat & 1) * 8 + r) * HROW + (mat >> 1) * 16);
    uint32_t b_off = (uint32_t)(((mat >> 1) * 8 + r) * HROW + (mat & 1) * 16);

    float c[4][8][4];
    #pragma unroll
    for (int mt = 0; mt < 4; mt++)
        #pragma unroll
        for (int nt = 0; nt < 8; nt++)
            #pragma unroll
            for (int e = 0; e < 4; e++) c[mt][nt][e] = 0.f;

    const int ldrow = tid >> 3;        // 0..31
    const int c16   = tid & 7;         // 16B chunk (8 halves)

    auto load_tile = [&](int t, int which) {
        int kb = t * 64;
        uint32_t ab = sb + (uint32_t)which * STGB;
        uint32_t wb = ab + ASTGB;
        #pragma unroll
        for (int i = 0; i < 4; i++) {          // A: 128 rows
            int row = ldrow + i * 32;
            cpa16(ab + row * HROW + c16 * 16,
                  A + (size_t)(bm + row) * K + kb + c16 * 8, 16);
        }
        #pragma unroll
        for (int i = 0; i < 8; i++) {          // B: 256 rows
            int row = ldrow + i * 32;
            int n = bn + row;
            int nn = n < N ? n : (N - 1);
            cpa16(wb + row * HROW + c16 * 16,
                  W + (size_t)nn * K + kb + c16 * 8, n < N ? 16 : 0);
        }
    };

    int ntiles = K / 64;
    load_tile(0, 0); cpa_commit();
    load_tile(1, 1); cpa_commit();

    for (int t = 0; t < ntiles; t++) {
        int buf = t % 3;
        if (t + 1 < ntiles) cpa_wait1(); else cpa_wait0();
        __syncthreads();
        if (t + 2 < ntiles) { load_tile(t + 2, (t + 2) % 3); cpa_commit(); }
        uint32_t ab = sb + (uint32_t)buf * STGB;
        uint32_t wb = ab + ASTGB;
        uint32_t abase = ab + (uint32_t)wm * HROW + a_off;
        uint32_t bbase = wb + (uint32_t)wn * HROW + b_off;
        #pragma unroll
        for (int ks = 0; ks < 4; ks++) {
            uint32_t kbyte = (uint32_t)ks * 32;   // 16 halves
            uint32_t af[4][4], bf[8][2];
            #pragma unroll
            for (int mt = 0; mt < 4; mt++)
                LDSM4(af[mt][0], af[mt][1], af[mt][2], af[mt][3],
                      abase + (uint32_t)mt * 16 * HROW + kbyte);
            #pragma unroll
            for (int ntp = 0; ntp < 4; ntp++)
                LDSM4(bf[2*ntp][0], bf[2*ntp][1], bf[2*ntp+1][0], bf[2*ntp+1][1],
                      bbase + (uint32_t)ntp * 16 * HROW + kbyte);
            #pragma unroll
            for (int mt = 0; mt < 4; mt++)
                #pragma unroll
                for (int nt = 0; nt < 8; nt++) {
                    asm volatile(
                        "mma.sync.aligned.m16n8k16.row.col.f32.f16.f16.f32 "
                        "{%0,%1,%2,%3}, {%4,%5,%6,%7}, {%8,%9}, {%0,%1,%2,%3};\n"
                        : "+f"(c[mt][nt][0]), "+f"(c[mt][nt][1]),
                          "+f"(c[mt][nt][2]), "+f"(c[mt][nt][3])
                        : "r"(af[mt][0]), "r"(af[mt][1]), "r"(af[mt][2]), "r"(af[mt][3]),
                          "r"(bf[nt][0]), "r"(bf[nt][1]));
                }
        }
        __syncthreads();
    }

    // epilogue
    #pragma unroll
    for (int mt = 0; mt < 4; mt++) {
        int r0 = bm + wm + mt * 16 + grp;
        #pragma unroll
        for (int nt = 0; nt < 8; nt++) {
            int col = bn + wn + nt * 8 + 2 * tig;
            if (col < N) {
                float v0 = c[mt][nt][0], v1 = c[mt][nt][1];
                float v2 = c[mt][nt][2], v3 = c[mt][nt][3];
                size_t o0 = (size_t)r0 * N + col;
                size_t o1 = (size_t)(r0 + 8) * N + col;
                if (res) {
                    v0 += res[o0]; v1 += res[o0 + 1];
                    v2 += res[o1]; v3 += res[o1 + 1];
                }
                *(float2*)(C + o0) = make_float2(v0, v1);
                *(float2*)(C + o1) = make_float2(v2, v3);
            }
        }
    }
}

// ------------------------------ causal depthwise conv ----------------------
__global__ void conv1d_kernel(const float* __restrict__ zx, const float* __restrict__ cw,
                              const float* __restrict__ cb, float* __restrict__ xBC) {
    size_t idx = (size_t)blockIdx.x * blockDim.x + threadIdx.x;
    if (idx >= (size_t)MTOK * CONVD) return;
    int c = (int)(idx % CONVD);
    int m = (int)(idx / CONVD);
    int t = m & (LSEQ - 1);
    float acc = cb[c];
    #pragma unroll
    for (int j = 0; j < 4; j++) {
        int tt = t - 3 + j;
        if (tt >= 0)
            acc += cw[c * 4 + j] * zx[(size_t)(m - 3 + j) * DINPROJ + DINNER + c];
    }
    xBC[idx] = acc;
}

// ------------------------------ SSD intra-chunk ----------------------------
__global__ void ssd_intra_kernel(const float* __restrict__ zx, const float* __restrict__ xBC,
                                 float* __restrict__ y, float* __restrict__ Sg,
                                 float* __restrict__ Ag, float* __restrict__ cumg) {
    extern __shared__ float sm[];
    float* xs   = sm;                       // 128*65
    float* Bs   = xs + CHUNK * 65;          // 128*65
    float* Cs   = Bs + CHUNK * 65;          // 128*65
    float* sc   = Cs + CHUNK * 65;          // 128*129
    float* cum  = sc + CHUNK * 129;         // 128
    float* dend = cum + CHUNK;              // 128

    int h = blockIdx.x % NH;
    int c = (blockIdx.x / NH) % NCHUNK;
    int b = blockIdx.x / (NH * NCHUNK);
    int tid = threadIdx.x;
    int m0 = b * LSEQ + c * CHUNK;

    for (int idx = tid; idx < CHUNK * HD; idx += 256) {
        int i = idx >> 6, p = idx & 63;
        size_t rowb = (size_t)(m0 + i) * CONVD;
        xs[i * 65 + p] = xBC[rowb + h * HD + p];
        Bs[i * 65 + p] = xBC[rowb + DINNER + h * DSTATE + p];
        Cs[i * 65 + p] = xBC[rowb + DINNER + NH * DSTATE + h * DSTATE + p];
    }
    if (tid < CHUNK) {
        float d = zx[(size_t)(m0 + tid) * DINPROJ + DTOFF + h];
        float sp = (d > 20.f) ? d : log1pf(expf(d));
        cum[tid] = -sp;
    }
    __syncthreads();
    for (int off = 1; off < CHUNK; off <<= 1) {
        float v = 0.f;
        if (tid < CHUNK && tid >= off) v = cum[tid - off];
        __syncthreads();
        if (tid < CHUNK && tid >= off) cum[tid] += v;
        __syncthreads();
    }
    if (tid < CHUNK) dend[tid] = expf(cum[CHUNK - 1] - cum[tid]);
    __syncthreads();

    int ty = tid >> 4, tx = tid & 15;
    {
        float acc[8][8];
        #pragma unroll
        for (int rr = 0; rr < 8; rr++)
            #pragma unroll
            for (int s = 0; s < 8; s++) acc[rr][s] = 0.f;
        int i0 = ty * 8;
        for (int n = 0; n < DSTATE; n++) {
            float cf[8], bf[8];
            #pragma unroll
            for (int rr = 0; rr < 8; rr++) cf[rr] = Cs[(i0 + rr) * 65 + n];
            #pragma unroll
            for (int s = 0; s < 8; s++) bf[s] = Bs[(tx + 16 * s) * 65 + n];
            #pragma unroll
            for (int rr = 0; rr < 8; rr++)
                #pragma unroll
                for (int s = 0; s < 8; s++) acc[rr][s] += cf[rr] * bf[s];
        }
        #pragma unroll
        for (int rr = 0; rr < 8; rr++) {
            int i = i0 + rr;
            float ci = cum[i];
            #pragma unroll
            for (int s = 0; s < 8; s++) {
                int j = tx + 16 * s;
                sc[i * 129 + j] = (j <= i) ? expf(ci - cum[j]) * acc[rr][s] : 0.f;
            }
        }
    }
    __syncthreads();
    {
        float acc[8][4];
        #pragma unroll
        for (int rr = 0; rr < 8; rr++)
            #pragma unroll
            for (int cc = 0; cc < 4; cc++) acc[rr][cc] = 0.f;
        int i0 = ty * 8, p0 = tx * 4;
        for (int j = 0; j < CHUNK; j++) {
            float xv[4];
            #pragma unroll
            for (int cc = 0; cc < 4; cc++) xv[cc] = xs[j * 65 + p0 + cc];
            #pragma unroll
            for (int rr = 0; rr < 8; rr++) {
                float sf = sc[(i0 + rr) * 129 + j];
                #pragma unroll
                for (int cc = 0; cc < 4; cc++) acc[rr][cc] += sf * xv[cc];
            }
        }
        #pragma unroll
        for (int rr = 0; rr < 8; rr++) {
            size_t ybase = (size_t)(m0 + i0 + rr) * DINNER + h * HD + p0;
            #pragma unroll
            for (int cc = 0; cc < 4; cc++) y[ybase + cc] = acc[rr][cc];
        }
    }
    {
        int n = tid >> 2;
        int p0 = (tid & 3) * 16;
        float acc[16];
        #pragma unroll
        for (int cc = 0; cc < 16; cc++) acc[cc] = 0.f;
        for (int j = 0; j < CHUNK; j++) {
            float w = dend[j] * Bs[j * 65 + n];
            #pragma unroll
            for (int cc = 0; cc < 16; cc++) acc[cc] += w * xs[j * 65 + p0 + cc];
        }
        size_t off = ((size_t)((b * NCHUNK + c) * NH + h)) * (DSTATE * HD) + n * HD + p0;
        #pragma unroll
        for (int cc = 0; cc < 16; cc++) Sg[off + cc] = acc[cc];
        if (tid == 0) Ag[(b * NCHUNK + c) * NH + h] = expf(cum[CHUNK - 1]);
    }
    if (tid < CHUNK)
        cumg[((size_t)((b * NCHUNK + c) * NH + h)) * CHUNK + tid] = cum[tid];
}

// ------------------------------ inter-chunk state recurrence ----------------
__global__ void state_scan_kernel(const float* __restrict__ Sg, const float* __restrict__ Ag,
                                  float* __restrict__ Hp) {
    int b = blockIdx.x / NH, h = blockIdx.x % NH;
    int tid = threadIdx.x;
    float H[16];
    #pragma unroll
    for (int k = 0; k < 16; k++) H[k] = 0.f;
    for (int c = 0; c < NCHUNK; c++) {
        size_t off = ((size_t)((b * NCHUNK + c) * NH + h)) * (DSTATE * HD);
        float Ac = Ag[(b * NCHUNK + c) * NH + h];
        #pragma unroll
        for (int k = 0; k < 16; k++) {
            int e = tid + k * 256;
            Hp[off + e] = H[k];
            H[k] = Ac * H[k] + Sg[off + e];
        }
    }
}

// ------------------------------ y_inter + D*x + gating (fp16 out) ----------
__global__ void y_inter_kernel(const float* __restrict__ zx, const float* __restrict__ xBC,
                               const float* __restrict__ Hp, const float* __restrict__ cumg,
                               const float* __restrict__ Dvec, const float* __restrict__ zb,
                               const float* __restrict__ y, __half* __restrict__ yh) {
    extern __shared__ float sm[];
    float* Cs  = sm;                  // 128*65
    float* xs  = Cs + CHUNK * 65;     // 128*65
    float* Hs  = xs + CHUNK * 65;     // 64*65
    float* cum = Hs + DSTATE * 65;    // 128

    int h = blockIdx.x % NH;
    int c = (blockIdx.x / NH) % NCHUNK;
    int b = blockIdx.x / (NH * NCHUNK);
    int tid = threadIdx.x;
    int m0 = b * LSEQ + c * CHUNK;
    size_t hoff = (size_t)((b * NCHUNK + c) * NH + h);

    for (int idx = tid; idx < CHUNK * HD; idx += 256) {
        int i = idx >> 6, p = idx & 63;
        size_t rowb = (size_t)(m0 + i) * CONVD;
        xs[i * 65 + p] = xBC[rowb + h * HD + p];
        Cs[i * 65 + p] = xBC[rowb + DINNER + NH * DSTATE + h * DSTATE + p];
    }
    for (int idx = tid; idx < DSTATE * HD; idx += 256)
        Hs[(idx >> 6) * 65 + (idx & 63)] = Hp[hoff * (DSTATE * HD) + idx];
    if (tid < CHUNK) cum[tid] = cumg[hoff * CHUNK + tid];
    __syncthreads();

    int i = tid >> 1;
    int p0 = (tid & 1) * 32;
    float acc[32];
    #pragma unroll
    for (int cc = 0; cc < 32; cc++) acc[cc] = 0.f;
    for (int n = 0; n < DSTATE; n++) {
        float cv = Cs[i * 65 + n];
        #pragma unroll
        for (int cc = 0; cc < 32; cc++) acc[cc] += cv * Hs[n * 65 + p0 + cc];
    }
    float e = expf(cum[i]);
    float Dh = Dvec[h];
    int m = m0 + i;
    size_t ybase = (size_t)m * DINNER + h * HD;
    size_t zbase = (size_t)m * DINPROJ + h * HD;
    #pragma unroll
    for (int cc = 0; cc < 32; cc++) {
        int p = p0 + cc;
        float yt = y[ybase + p] + e * acc[cc] + Dh * xs[i * 65 + p];
        float g = zx[zbase + p] + zb[h * HD + p];
        float sg = g / (1.f + expf(-g));
        yh[ybase + p] = __float2half_rn(yt * sg);
    }
}

// ------------------------------ MLP elementwise (fp16 out) ------------------
__global__ void silu_mul_kernel(const float* __restrict__ gate, const float* __restrict__ up,
                                __half* __restrict__ act, size_t n) {
    size_t i = (size_t)blockIdx.x * blockDim.x + threadIdx.x;
    if (i < n) {
        float g = gate[i];
        act[i] = __float2half_rn((g / (1.f + expf(-g))) * up[i]);
    }
}

// ------------------------------ launch --------------------------------------
extern "C" void kernel_launch(void* const* d_in, const int* in_sizes, int n_in,
                              void* d_out, int out_size) {
    const float* hidden     = (const float*)d_in[0];
    const float* in_proj_w  = (const float*)d_in[1];
    const float* z_bias     = (const float*)d_in[2];
    const float* conv_w     = (const float*)d_in[3];
    const float* conv_b     = (const float*)d_in[4];
    const float* Dvec       = (const float*)d_in[5];
    const float* out_proj_w = (const float*)d_in[6];
    const float* norm1_w    = (const float*)d_in[7];
    const float* norm2_w    = (const float*)d_in[8];
    const float* gate_w     = (const float*)d_in[9];
    const float* up_w       = (const float*)d_in[10];
    const float* down_w     = (const float*)d_in[11];
    float* out = (float*)d_out;

    float *zx, *xbc, *y, *S, *A, *cumg, *Hp, *h2, *gate, *up;
    __half *h1h, *yh, *h3h, *acth, *wip, *wop, *wg, *wu, *wd;
    cudaGetSymbolAddress((void**)&zx,   g_zx);
    cudaGetSymbolAddress((void**)&xbc,  g_xBC);
    cudaGetSymbolAddress((void**)&y,    g_y);
    cudaGetSymbolAddress((void**)&S,    g_S);
    cudaGetSymbolAddress((void**)&A,    g_Ac);
    cudaGetSymbolAddress((void**)&cumg, g_cum);
    cudaGetSymbolAddress((void**)&Hp,   g_Hp);
    cudaGetSymbolAddress((void**)&h2,   g_h2);
    cudaGetSymbolAddress((void**)&gate, g_gate);
    cudaGetSymbolAddress((void**)&up,   g_up);
    cudaGetSymbolAddress((void**)&h1h,  g_h1h);
    cudaGetSymbolAddress((void**)&yh,   g_yh);
    cudaGetSymbolAddress((void**)&h3h,  g_h3h);
    cudaGetSymbolAddress((void**)&acth, g_acth);
    cudaGetSymbolAddress((void**)&wip,  g_wip);
    cudaGetSymbolAddress((void**)&wop,  g_wop);
    cudaGetSymbolAddress((void**)&wg,   g_wg);
    cudaGetSymbolAddress((void**)&wu,   g_wu);
    cudaGetSymbolAddress((void**)&wd,   g_wd);

    const int SMEM_INTRA  = (3 * CHUNK * 65 + CHUNK * 129 + 2 * CHUNK) * sizeof(float);
    const int SMEM_YINTER = (2 * CHUNK * 65 + DSTATE * 65 + CHUNK) * sizeof(float);
    cudaFuncSetAttribute(ssd_intra_kernel, cudaFuncAttributeMaxDynamicSharedMemorySize, SMEM_INTRA);
    cudaFuncSetAttribute(y_inter_kernel,  cudaFuncAttributeMaxDynamicSharedMemorySize, SMEM_YINTER);
    cudaFuncSetAttribute(hgemm_kernel,    cudaFuncAttributeMaxDynamicSharedMemorySize, SMEM_HGEMM);

    // 0) convert weights fp32 -> fp16
    {
        auto cc = [&](const float* src, __half* dst, size_t n) {
            int n4 = (int)(n / 4);
            w2h_kernel<<<(n4 + 255) / 256, 256>>>(src, dst, n4);
        };
        cc(in_proj_w,  wip, (size_t)DINPROJ * DMODEL);
        cc(out_proj_w, wop, (size_t)DMODEL * DINNER);
        cc(gate_w,     wg,  (size_t)DFF * DMODEL);
        cc(up_w,       wu,  (size_t)DFF * DMODEL);
        cc(down_w,     wd,  (size_t)DMODEL * DFF);
    }

    // 1) rmsnorm 1 -> fp16
    rmsnorm_kernel<<<MTOK, 256>>>(hidden, norm1_w, h1h);
    // 2) in_proj: zx = h1 @ in_proj_w^T   [4096 x 8224]
    hgemm_kernel<<<dim3((DINPROJ + 255) / 256, MTOK / 128), 256, SMEM_HGEMM>>>(
        h1h, wip, nullptr, zx, MTOK, DINPROJ, DMODEL);
    // 3) causal depthwise conv
    conv1d_kernel<<<(int)(((size_t)MTOK * CONVD + 255) / 256), 256>>>(zx, conv_w, conv_b, xbc);
    // 4) SSD intra-chunk
    ssd_intra_kernel<<<BATCH * NCHUNK * NH, 256, SMEM_INTRA>>>(zx, xbc, y, S, A, cumg);
    // 5) inter-chunk state recurrence
    state_scan_kernel<<<BATCH * NH, 256>>>(S, A, Hp);
    // 6) y_inter + D*x + gating -> fp16
    y_inter_kernel<<<BATCH * NCHUNK * NH, 256, SMEM_YINTER>>>(
        zx, xbc, Hp, cumg, Dvec, z_bias, y, yh);
    // 7) out_proj + residual: h2 = y @ out_proj_w^T + hidden
    hgemm_kernel<<<dim3(DMODEL / 256, MTOK / 128), 256, SMEM_HGEMM>>>(
        yh, wop, hidden, h2, MTOK, DMODEL, DINNER);
    // 8) rmsnorm 2 -> fp16
    rmsnorm_kernel<<<MTOK, 256>>>(h2, norm2_w, h3h);
    // 9) MLP gate / up
    hgemm_kernel<<<dim3(DFF / 256, MTOK / 128), 256, SMEM_HGEMM>>>(
        h3h, wg, nullptr, gate, MTOK, DFF, DMODEL);
    hgemm_kernel<<<dim3(DFF / 256, MTOK / 128), 256, SMEM_HGEMM>>>(
        h3h, wu, nullptr, up, MTOK, DFF, DMODEL);
    // 10) act = silu(gate) * up -> fp16
    silu_mul_kernel<<<(int)(((size_t)MTOK * DFF + 255) / 256), 256>>>(
        gate, up, acth, (size_t)MTOK * DFF);
    // 11) down + residual: out = act @ down_w^T + h2
    hgemm_kernel<<<dim3(DMODEL / 256, MTOK / 128), 256, SMEM_HGEMM>>>(
        acth, wd, h2, out, MTOK, DMODEL, DFF);
}